// round 4
// baseline (speedup 1.0000x reference)
#include <cuda_runtime.h>
#include <cuda_bf16.h>
#include <cstdint>

// Problem dims (fixed)
#define NB   256
#define LL   2048
#define QK   512
#define HH   128

#define ROWS_PER_CTA 256
#define SPLITS       (LL / ROWS_PER_CTA)    // 8
#define NCTAS        (NB * SPLITS)          // 2048
#define KCHUNK       32                     // floats -> 128B rows
#define NCHUNKS      (QK / KCHUNK)          // 16
#define THREADS      256
#define NSTAGE       4

#define A_STAGE_BYTES (ROWS_PER_CTA * 128)  // 32768
#define B_STAGE_BYTES (HH * 128)            // 16384

// smem byte offsets
#define SM_A     0
#define SM_B     (NSTAGE * A_STAGE_BYTES)              // 131072
#define SM_QS    (SM_B + NSTAGE * B_STAGE_BYTES)       // 196608
#define SM_VAS   (SM_QS + 512)
#define SM_ES    (SM_VAS + 512)
#define SM_PS    (SM_ES + 1024)
#define SM_RED   (SM_PS + 1024)
#define SM_CST   (SM_RED + 128)
#define SM_TOTAL (SM_CST + 2048)                        // 201856

// ---------------- device scratch ----------------
__device__ float g_p[NB * LL];
__device__ float g_pz[NCTAS];
__device__ float g_pc[(size_t)NCTAS * QK];
__device__ int   g_cnt[NB];                 // zero-init; self-resetting

// ---------------- helpers ----------------
__device__ __forceinline__ void cp16(uint32_t smem_addr, const float* src) {
    asm volatile("cp.async.cg.shared.global [%0], [%1], 16;\n" :: "r"(smem_addr), "l"(src));
}
__device__ __forceinline__ void cp_commit() { asm volatile("cp.async.commit_group;\n"); }
__device__ __forceinline__ void cp_wait2()  { asm volatile("cp.async.wait_group 2;\n"); }
__device__ __forceinline__ void cp_wait1()  { asm volatile("cp.async.wait_group 1;\n"); }
__device__ __forceinline__ void cp_wait0()  { asm volatile("cp.async.wait_group 0;\n"); }

__device__ __forceinline__ void mma_tf32(float* c, const uint32_t* a, const uint32_t* b) {
    asm volatile(
        "mma.sync.aligned.m16n8k8.row.col.f32.tf32.tf32.f32 "
        "{%0,%1,%2,%3},{%4,%5,%6,%7},{%8,%9},{%0,%1,%2,%3};"
        : "+f"(c[0]), "+f"(c[1]), "+f"(c[2]), "+f"(c[3])
        : "r"(a[0]), "r"(a[1]), "r"(a[2]), "r"(a[3]), "r"(b[0]), "r"(b[1]));
}
__device__ __forceinline__ float tanh_fast(float x) {
    float y; asm("tanh.approx.f32 %0, %1;" : "=f"(y) : "f"(x)); return y;
}

// ---------------- single fused kernel ----------------
__global__ void __launch_bounds__(THREADS, 1)
k_fused(const float* __restrict__ X,            // (NB,LL,QK)
        const float* __restrict__ Ua,           // (HH,QK)
        const float* __restrict__ va,           // (1,HH)
        const float* __restrict__ last_hidden,  // (NB,1,QK)
        const float* __restrict__ Wa,           // (HH,QK)
        float* __restrict__ out) {
    extern __shared__ char sm[];
    const uint32_t smem_u32 = (uint32_t)__cvta_generic_to_shared(sm);
    float* qs  = reinterpret_cast<float*>(sm + SM_QS);
    float* vas = reinterpret_cast<float*>(sm + SM_VAS);
    float* es  = reinterpret_cast<float*>(sm + SM_ES);
    float* ps  = reinterpret_cast<float*>(sm + SM_PS);
    float* red = reinterpret_cast<float*>(sm + SM_RED);
    float* cst = reinterpret_cast<float*>(sm + SM_CST);
    __shared__ int s_last;

    const int tid  = threadIdx.x;
    const int bx   = blockIdx.x;
    const int row0 = bx * ROWS_PER_CTA;
    const int n    = row0 >> 11;

    const int warp = tid >> 5;
    const int lane = tid & 31;
    const int wr = warp >> 1;          // 0..3 (64-row strip)
    const int wc = warp & 1;           // 0..1 (64-col strip)
    const int g  = lane >> 2;
    const int t  = lane & 3;
    const int xm = g << 4;             // swizzle xor mask for fragment loads

    es[tid] = 0.f;
    if (tid < HH) vas[tid] = va[tid];

    // ---- chunk loader: cp.async into XOR-swizzled 128B rows ----
    auto load_chunk = [&](int kc, int stage) {
        const uint32_t abase = smem_u32 + SM_A + stage * A_STAGE_BYTES;
        const uint32_t bbase = smem_u32 + SM_B + stage * B_STAGE_BYTES;
        const float* Xs  = X  + (size_t)row0 * QK + kc * KCHUNK;
        const float* Uas = Ua + kc * KCHUNK;
#pragma unroll
        for (int i = 0; i < 8; ++i) {                  // A: 2048 x 16B
            int v = tid + i * THREADS;
            int r = v >> 3, s = v & 7;
            cp16(abase + (uint32_t)(r * 128 + ((s * 16) ^ ((r & 7) << 4))),
                 Xs + (size_t)r * QK + s * 4);
        }
#pragma unroll
        for (int i = 0; i < 4; ++i) {                  // B: 1024 x 16B
            int v = tid + i * THREADS;
            int r = v >> 3, s = v & 7;
            cp16(bbase + (uint32_t)(r * 128 + ((s * 16) ^ ((r & 7) << 4))),
                 Uas + (size_t)r * QK + s * 4);
        }
    };

    // prologue: 3 chunks in flight
    load_chunk(0, 0); cp_commit();
    load_chunk(1, 1); cp_commit();
    load_chunk(2, 2); cp_commit();

    // ---- q projection (hidden under prologue loads) ----
    // thread (h = tid>>1, half = tid&1): 256-elem dot, pair-reduce via shfl
    {
        const int h = tid >> 1, half = tid & 1;
        const float4* w4 = reinterpret_cast<const float4*>(Wa + (size_t)h * QK + half * 256);
        const float4* x4 = reinterpret_cast<const float4*>(last_hidden + (size_t)n * QK + half * 256);
        float a0 = 0.f, a1 = 0.f, a2 = 0.f, a3 = 0.f;
#pragma unroll 4
        for (int i = 0; i < 64; i += 4) {
            float4 w0 = w4[i+0], x0 = x4[i+0];
            float4 w1 = w4[i+1], x1 = x4[i+1];
            float4 w2 = w4[i+2], x2 = x4[i+2];
            float4 w3 = w4[i+3], x3 = x4[i+3];
            a0 += w0.x*x0.x + w0.y*x0.y + w0.z*x0.z + w0.w*x0.w;
            a1 += w1.x*x1.x + w1.y*x1.y + w1.z*x1.z + w1.w*x1.w;
            a2 += w2.x*x2.x + w2.y*x2.y + w2.z*x2.z + w2.w*x2.w;
            a3 += w3.x*x3.x + w3.y*x3.y + w3.z*x3.z + w3.w*x3.w;
        }
        float s = (a0 + a1) + (a2 + a3);
        s += __shfl_xor_sync(0xffffffffu, s, 1);
        if (half == 0) qs[h] = s;
    }

    float acc[4][8][4];
#pragma unroll
    for (int m = 0; m < 4; ++m)
#pragma unroll
        for (int j = 0; j < 8; ++j)
#pragma unroll
            for (int c = 0; c < 4; ++c) acc[m][j][c] = 0.f;

    // ---- mainloop: 4-stage, distance-3 prefetch ----
#pragma unroll 1
    for (int kc = 0; kc < NCHUNKS; ++kc) {
        if (kc <= NCHUNKS - 3)      cp_wait2();   // group kc complete
        else if (kc == NCHUNKS - 2) cp_wait1();
        else                        cp_wait0();
        __syncthreads();

        const int stage = kc & 3;
        const char* Ab = sm + SM_A + stage * A_STAGE_BYTES;
        const char* Bb = sm + SM_B + stage * B_STAGE_BYTES;

#pragma unroll
        for (int ks = 0; ks < 4; ++ks) {
            const int k0 = ks * 8;
            const int cb0 = ((k0 + t) * 4) ^ xm;
            const int cb1 = ((k0 + t + 4) * 4) ^ xm;
            uint32_t bu[8][2];
#pragma unroll
            for (int j = 0; j < 8; ++j) {
                const char* br = Bb + (wc * 64 + j * 8 + g) * 128;
                bu[j][0] = *reinterpret_cast<const uint32_t*>(br + cb0);
                bu[j][1] = *reinterpret_cast<const uint32_t*>(br + cb1);
            }
#pragma unroll
            for (int m = 0; m < 4; ++m) {
                const char* ar0 = Ab + (wr * 64 + m * 16 + g) * 128;
                const char* ar1 = ar0 + 8 * 128;
                uint32_t au[4];
                au[0] = *reinterpret_cast<const uint32_t*>(ar0 + cb0);
                au[1] = *reinterpret_cast<const uint32_t*>(ar1 + cb0);
                au[2] = *reinterpret_cast<const uint32_t*>(ar0 + cb1);
                au[3] = *reinterpret_cast<const uint32_t*>(ar1 + cb1);
#pragma unroll
                for (int j = 0; j < 8; ++j) mma_tf32(acc[m][j], au, bu[j]);
            }
            // prefetch chunk kc+3 into stage (kc+3)&3 (freed: computed at kc-1)
            if (ks == 0 && kc + 3 < NCHUNKS) {
                load_chunk(kc + 3, (kc + 3) & 3);
                cp_commit();
            }
        }
    }

    // ---- epilogue: e_r = sum_h va[h] * tanh(q[h] + C[r,h]) ----
#pragma unroll
    for (int m = 0; m < 4; ++m) {
#pragma unroll
        for (int rr = 0; rr < 2; ++rr) {
            float pa = 0.f;
#pragma unroll
            for (int j = 0; j < 8; ++j) {
#pragma unroll
                for (int cc = 0; cc < 2; ++cc) {
                    int h = wc * 64 + j * 8 + t * 2 + cc;
                    pa += vas[h] * tanh_fast(qs[h] + acc[m][j][rr * 2 + cc]);
                }
            }
            pa += __shfl_xor_sync(0xffffffffu, pa, 1);
            pa += __shfl_xor_sync(0xffffffffu, pa, 2);
            if (t == 0) atomicAdd(&es[wr * 64 + m * 16 + rr * 8 + g], pa);
        }
    }
    __syncthreads();

    // energies bounded (|e| <= sum|va| ~= 11): exp without max-pass is safe
    float p = __expf(es[tid]);
    ps[tid] = p;
    g_p[row0 + tid] = p;

    float s = p;
#pragma unroll
    for (int o = 16; o > 0; o >>= 1) s += __shfl_xor_sync(0xffffffffu, s, o);
    if (lane == 0) red[warp] = s;
    __syncthreads();
    if (tid == 0) {
        float Z = 0.f;
#pragma unroll
        for (int i = 0; i < 8; ++i) Z += red[i];
        g_pz[bx] = Z;
    }
    __syncthreads();   // ps[] visible

    // ---- partial context (L2 re-read of this CTA's tile) ----
    {
        const int c4 = (tid & 127) * 4;
        const int rh = tid >> 7;
        const float* Xp = X + (size_t)(row0 + rh * 128) * QK + c4;
        float4 a = make_float4(0.f, 0.f, 0.f, 0.f);
#pragma unroll 4
        for (int l = 0; l < 128; ++l) {
            float pl = ps[rh * 128 + l];
            float4 x = *reinterpret_cast<const float4*>(Xp + (size_t)l * QK);
            a.x += pl * x.x; a.y += pl * x.y; a.z += pl * x.z; a.w += pl * x.w;
        }
        if (rh == 1) *reinterpret_cast<float4*>(cst + c4) = a;
        __syncthreads();
        if (rh == 0) {
            float4 b = *reinterpret_cast<const float4*>(cst + c4);
            a.x += b.x; a.y += b.y; a.z += b.z; a.w += b.w;
            *reinterpret_cast<float4*>(&g_pc[(size_t)bx * QK + c4]) = a;
        }
    }

    // ---- fan-in: last CTA of the batch combines ----
    __syncthreads();
    if (tid == 0) {
        __threadfence();
        int old = atomicAdd(&g_cnt[n], 1);
        s_last = (old == SPLITS - 1) ? 1 : 0;
    }
    __syncthreads();
    if (s_last) {
        __threadfence();   // acquire other splits' writes
        float Z = 0.f;
#pragma unroll
        for (int i = 0; i < SPLITS; ++i) Z += g_pz[n * SPLITS + i];
        const float rZ = 1.f / Z;

        float* ctx = out;                       // (NB, QK)
        float* wts = out + (size_t)NB * QK;     // (NB, LL)
#pragma unroll
        for (int dd = 0; dd < 2; ++dd) {
            int d = tid + dd * 256;
            float c = 0.f;
#pragma unroll
            for (int i = 0; i < SPLITS; ++i)
                c += g_pc[(size_t)(n * SPLITS + i) * QK + d];
            ctx[(size_t)n * QK + d] = c * rZ;
        }
#pragma unroll
        for (int i = 0; i < LL / 256; ++i) {
            int l = tid + i * 256;
            wts[(size_t)n * LL + l] = g_p[(size_t)n * LL + l] * rZ;
        }
        if (tid == 0) g_cnt[n] = 0;   // self-reset for next replay
    }
}

// ---------------- launch ----------------
extern "C" void kernel_launch(void* const* d_in, const int* in_sizes, int n_in,
                              void* d_out, int out_size) {
    const float* last_hidden     = (const float*)d_in[0];
    const float* encoder_outputs = (const float*)d_in[1];
    const float* Wa              = (const float*)d_in[2];
    const float* Ua              = (const float*)d_in[3];
    const float* va              = (const float*)d_in[4];
    float* out = (float*)d_out;

    static bool attr_set = false;
    if (!attr_set) {
        cudaFuncSetAttribute(k_fused, cudaFuncAttributeMaxDynamicSharedMemorySize, SM_TOTAL);
        attr_set = true;
    }

    k_fused<<<NCTAS, THREADS, SM_TOTAL>>>(encoder_outputs, Ua, va, last_hidden, Wa, out);
}

// round 5
// speedup vs baseline: 1.3727x; 1.3727x over previous
#include <cuda_runtime.h>
#include <cuda_bf16.h>
#include <cstdint>

// Problem dims (fixed)
#define NB   256
#define LL   2048
#define QK   512
#define HH   128

#define ROWS_PER_CTA 256
#define SPLITS       (LL / ROWS_PER_CTA)    // 8
#define NCTAS        (NB * SPLITS)          // 2048
#define KCHUNK       32                     // floats -> 128B rows
#define NCHUNKS      (QK / KCHUNK)          // 16
#define THREADS      512
#define NSTAGE       4

#define A_STAGE_BYTES (ROWS_PER_CTA * 128)  // 32768
#define B_STAGE_BYTES (HH * 128)            // 16384

// smem byte offsets
#define SM_A     0
#define SM_B     (NSTAGE * A_STAGE_BYTES)              // 131072
#define SM_QS    (SM_B + NSTAGE * B_STAGE_BYTES)       // 196608
#define SM_VAS   (SM_QS + 512)
#define SM_ES    (SM_VAS + 512)
#define SM_PS    (SM_ES + 1024)
#define SM_RED   (SM_PS + 1024)
#define SM_CST   (SM_RED + 128)                        // 3 partial ctx slices
#define SM_TOTAL (SM_CST + 3 * 2048)                   // ~204 KB

// ---------------- device scratch ----------------
__device__ float g_p[NB * LL];
__device__ float g_pz[NCTAS];
__device__ float g_pc[(size_t)NCTAS * QK];
__device__ int   g_cnt[NB];                 // zero-init; self-resetting

// ---------------- helpers ----------------
__device__ __forceinline__ void cp16(uint32_t smem_addr, const float* src) {
    asm volatile("cp.async.cg.shared.global [%0], [%1], 16;\n" :: "r"(smem_addr), "l"(src));
}
__device__ __forceinline__ void cp_commit() { asm volatile("cp.async.commit_group;\n"); }
__device__ __forceinline__ void cp_wait2()  { asm volatile("cp.async.wait_group 2;\n"); }
__device__ __forceinline__ void cp_wait1()  { asm volatile("cp.async.wait_group 1;\n"); }
__device__ __forceinline__ void cp_wait0()  { asm volatile("cp.async.wait_group 0;\n"); }

__device__ __forceinline__ void mma_tf32(float* c, const uint32_t* a, const uint32_t* b) {
    asm volatile(
        "mma.sync.aligned.m16n8k8.row.col.f32.tf32.tf32.f32 "
        "{%0,%1,%2,%3},{%4,%5,%6,%7},{%8,%9},{%0,%1,%2,%3};"
        : "+f"(c[0]), "+f"(c[1]), "+f"(c[2]), "+f"(c[3])
        : "r"(a[0]), "r"(a[1]), "r"(a[2]), "r"(a[3]), "r"(b[0]), "r"(b[1]));
}
__device__ __forceinline__ float tanh_fast(float x) {
    float y; asm("tanh.approx.f32 %0, %1;" : "=f"(y) : "f"(x)); return y;
}

// ---------------- single fused kernel ----------------
__global__ void __launch_bounds__(THREADS, 1)
k_fused(const float* __restrict__ X,            // (NB,LL,QK)
        const float* __restrict__ Ua,           // (HH,QK)
        const float* __restrict__ va,           // (1,HH)
        const float* __restrict__ last_hidden,  // (NB,1,QK)
        const float* __restrict__ Wa,           // (HH,QK)
        float* __restrict__ out) {
    extern __shared__ char sm[];
    const uint32_t smem_u32 = (uint32_t)__cvta_generic_to_shared(sm);
    float* qs  = reinterpret_cast<float*>(sm + SM_QS);
    float* vas = reinterpret_cast<float*>(sm + SM_VAS);
    float* es  = reinterpret_cast<float*>(sm + SM_ES);
    float* ps  = reinterpret_cast<float*>(sm + SM_PS);
    float* red = reinterpret_cast<float*>(sm + SM_RED);
    float* cst = reinterpret_cast<float*>(sm + SM_CST);
    __shared__ int s_last;

    const int tid  = threadIdx.x;
    const int bx   = blockIdx.x;
    const int row0 = bx * ROWS_PER_CTA;
    const int n    = row0 >> 11;

    const int warp = tid >> 5;
    const int lane = tid & 31;
    const int wr = warp >> 2;          // 0..3 : 64-row strip
    const int wc = warp & 3;           // 0..3 : 32-col strip
    const int g  = lane >> 2;
    const int t  = lane & 3;
    const int xm = g << 4;             // swizzle xor for fragment loads

    if (tid < ROWS_PER_CTA) es[tid] = 0.f;
    if (tid < HH) vas[tid] = va[tid];

    // ---- chunk loader: cp.async into XOR-swizzled 128B rows ----
    auto load_chunk = [&](int kc, int stage) {
        const uint32_t abase = smem_u32 + SM_A + stage * A_STAGE_BYTES;
        const uint32_t bbase = smem_u32 + SM_B + stage * B_STAGE_BYTES;
        const float* Xs  = X  + (size_t)row0 * QK + kc * KCHUNK;
        const float* Uas = Ua + kc * KCHUNK;
#pragma unroll
        for (int i = 0; i < 4; ++i) {                  // A: 2048 x 16B
            int v = tid + i * THREADS;
            int r = v >> 3, s = v & 7;
            cp16(abase + (uint32_t)(r * 128 + ((s * 16) ^ ((r & 7) << 4))),
                 Xs + (size_t)r * QK + s * 4);
        }
#pragma unroll
        for (int i = 0; i < 2; ++i) {                  // B: 1024 x 16B
            int v = tid + i * THREADS;
            int r = v >> 3, s = v & 7;
            cp16(bbase + (uint32_t)(r * 128 + ((s * 16) ^ ((r & 7) << 4))),
                 Uas + (size_t)r * QK + s * 4);
        }
    };

    // prologue: 3 chunks in flight
    load_chunk(0, 0); cp_commit();
    load_chunk(1, 1); cp_commit();
    load_chunk(2, 2); cp_commit();

    // ---- q projection, coalesced: each warp does 8 rows, lanes stride the row ----
    {
        const float4* x4 = reinterpret_cast<const float4*>(last_hidden + (size_t)n * QK);
        float4 xv[4];
#pragma unroll
        for (int k = 0; k < 4; ++k) xv[k] = x4[lane + k * 32];
#pragma unroll
        for (int rr = 0; rr < 8; ++rr) {
            const int h = warp * 8 + rr;
            const float4* w4 = reinterpret_cast<const float4*>(Wa + (size_t)h * QK);
            float a = 0.f;
#pragma unroll
            for (int k = 0; k < 4; ++k) {
                float4 w = w4[lane + k * 32];
                a += w.x * xv[k].x + w.y * xv[k].y + w.z * xv[k].z + w.w * xv[k].w;
            }
#pragma unroll
            for (int o = 16; o > 0; o >>= 1) a += __shfl_xor_sync(0xffffffffu, a, o);
            if (lane == 0) qs[h] = a;
        }
    }

    float acc[4][4][4];
#pragma unroll
    for (int m = 0; m < 4; ++m)
#pragma unroll
        for (int j = 0; j < 4; ++j)
#pragma unroll
            for (int c = 0; c < 4; ++c) acc[m][j][c] = 0.f;

    // ---- mainloop: 4-stage, distance-3 prefetch ----
#pragma unroll 1
    for (int kc = 0; kc < NCHUNKS; ++kc) {
        if (kc <= NCHUNKS - 3)      cp_wait2();   // group kc complete
        else if (kc == NCHUNKS - 2) cp_wait1();
        else                        cp_wait0();
        __syncthreads();

        const int stage = kc & 3;
        const char* Ab = sm + SM_A + stage * A_STAGE_BYTES;
        const char* Bb = sm + SM_B + stage * B_STAGE_BYTES;

#pragma unroll
        for (int ks = 0; ks < 4; ++ks) {
            const int k0 = ks * 8;
            const int cb0 = ((k0 + t) * 4) ^ xm;
            const int cb1 = ((k0 + t + 4) * 4) ^ xm;
            uint32_t bu[4][2];
#pragma unroll
            for (int j = 0; j < 4; ++j) {
                const char* br = Bb + (wc * 32 + j * 8 + g) * 128;
                bu[j][0] = *reinterpret_cast<const uint32_t*>(br + cb0);
                bu[j][1] = *reinterpret_cast<const uint32_t*>(br + cb1);
            }
#pragma unroll
            for (int m = 0; m < 4; ++m) {
                const char* ar0 = Ab + (wr * 64 + m * 16 + g) * 128;
                const char* ar1 = ar0 + 8 * 128;
                uint32_t au[4];
                au[0] = *reinterpret_cast<const uint32_t*>(ar0 + cb0);
                au[1] = *reinterpret_cast<const uint32_t*>(ar1 + cb0);
                au[2] = *reinterpret_cast<const uint32_t*>(ar0 + cb1);
                au[3] = *reinterpret_cast<const uint32_t*>(ar1 + cb1);
#pragma unroll
                for (int j = 0; j < 4; ++j) mma_tf32(acc[m][j], au, bu[j]);
            }
            // prefetch chunk kc+3 into stage (kc+3)&3 == (kc-1)&3 (freed at this barrier)
            if (ks == 0 && kc + 3 < NCHUNKS) {
                load_chunk(kc + 3, (kc + 3) & 3);
                cp_commit();
            }
        }
    }

    // ---- epilogue: e_r = sum_h va[h] * tanh(q[h] + C[r,h]) ----
#pragma unroll
    for (int m = 0; m < 4; ++m) {
#pragma unroll
        for (int rr = 0; rr < 2; ++rr) {
            float pa = 0.f;
#pragma unroll
            for (int j = 0; j < 4; ++j) {
#pragma unroll
                for (int cc = 0; cc < 2; ++cc) {
                    int h = wc * 32 + j * 8 + t * 2 + cc;
                    pa += vas[h] * tanh_fast(qs[h] + acc[m][j][rr * 2 + cc]);
                }
            }
            pa += __shfl_xor_sync(0xffffffffu, pa, 1);
            pa += __shfl_xor_sync(0xffffffffu, pa, 2);
            if (t == 0) atomicAdd(&es[wr * 64 + m * 16 + rr * 8 + g], pa);
        }
    }
    __syncthreads();

    // energies bounded (|e| <= sum|va| ~= 11): exp without max-pass is safe
    if (tid < ROWS_PER_CTA) {
        float p = __expf(es[tid]);
        ps[tid] = p;
        g_p[row0 + tid] = p;
        float s = p;
#pragma unroll
        for (int o = 16; o > 0; o >>= 1) s += __shfl_xor_sync(0xffffffffu, s, o);
        if (lane == 0) red[warp] = s;
    }
    __syncthreads();
    if (tid == 0) {
        float Z = 0.f;
#pragma unroll
        for (int i = 0; i < 8; ++i) Z += red[i];
        g_pz[bx] = Z;
    }
    __syncthreads();   // ps[] visible

    // ---- partial context: 4 row-quarters of 64, then smem tree-sum ----
    {
        const int c4 = (tid & 127) * 4;
        const int qt = tid >> 7;                 // 0..3
        const float* Xp = X + (size_t)(row0 + qt * 64) * QK + c4;
        float4 a = make_float4(0.f, 0.f, 0.f, 0.f);
#pragma unroll 4
        for (int l = 0; l < 64; ++l) {
            float pl = ps[qt * 64 + l];
            float4 x = *reinterpret_cast<const float4*>(Xp + (size_t)l * QK);
            a.x += pl * x.x; a.y += pl * x.y; a.z += pl * x.z; a.w += pl * x.w;
        }
        if (qt >= 1) *reinterpret_cast<float4*>(cst + (qt - 1) * QK + c4) = a;
        __syncthreads();
        if (qt == 0) {
#pragma unroll
            for (int i = 0; i < 3; ++i) {
                float4 b = *reinterpret_cast<const float4*>(cst + i * QK + c4);
                a.x += b.x; a.y += b.y; a.z += b.z; a.w += b.w;
            }
            *reinterpret_cast<float4*>(&g_pc[(size_t)bx * QK + c4]) = a;
        }
    }

    // ---- fan-in: last CTA of the batch combines ----
    __syncthreads();
    if (tid == 0) {
        __threadfence();
        int old = atomicAdd(&g_cnt[n], 1);
        s_last = (old == SPLITS - 1) ? 1 : 0;
    }
    __syncthreads();
    if (s_last) {
        __threadfence();
        float Z = 0.f;
#pragma unroll
        for (int i = 0; i < SPLITS; ++i) Z += g_pz[n * SPLITS + i];
        const float rZ = 1.f / Z;

        float* ctx = out;                       // (NB, QK)
        float* wts = out + (size_t)NB * QK;     // (NB, LL)
        {
            int d = tid;                         // QK == THREADS
            float c = 0.f;
#pragma unroll
            for (int i = 0; i < SPLITS; ++i)
                c += g_pc[(size_t)(n * SPLITS + i) * QK + d];
            ctx[(size_t)n * QK + d] = c * rZ;
        }
#pragma unroll
        for (int i = 0; i < LL / THREADS; ++i) {
            int l = tid + i * THREADS;
            wts[(size_t)n * LL + l] = g_p[(size_t)n * LL + l] * rZ;
        }
        if (tid == 0) g_cnt[n] = 0;   // self-reset for next replay
    }
}

// ---------------- launch ----------------
extern "C" void kernel_launch(void* const* d_in, const int* in_sizes, int n_in,
                              void* d_out, int out_size) {
    const float* last_hidden     = (const float*)d_in[0];
    const float* encoder_outputs = (const float*)d_in[1];
    const float* Wa              = (const float*)d_in[2];
    const float* Ua              = (const float*)d_in[3];
    const float* va              = (const float*)d_in[4];
    float* out = (float*)d_out;

    static bool attr_set = false;
    if (!attr_set) {
        cudaFuncSetAttribute(k_fused, cudaFuncAttributeMaxDynamicSharedMemorySize, SM_TOTAL);
        attr_set = true;
    }

    k_fused<<<NCTAS, THREADS, SM_TOTAL>>>(encoder_outputs, Ua, va, last_hidden, Wa, out);
}

// round 6
// speedup vs baseline: 1.4809x; 1.0788x over previous
#include <cuda_runtime.h>
#include <cuda_bf16.h>
#include <cstdint>

// Problem dims (fixed)
#define NB   256
#define LL   2048
#define QK   512
#define HH   128

#define ROWS_PER_CTA 128
#define SPLITS       (LL / ROWS_PER_CTA)    // 16
#define NCTAS        (NB * SPLITS)          // 4096
#define KCHUNK       32                     // floats -> 128B rows
#define NCHUNKS      (QK / KCHUNK)          // 16
#define THREADS      256
#define NSTAGE       3

#define A_STAGE_BYTES (ROWS_PER_CTA * 128)  // 16384
#define B_STAGE_BYTES (HH * 128)            // 16384

// smem byte offsets
#define SM_A     0
#define SM_B     (NSTAGE * A_STAGE_BYTES)              // 49152
#define SM_QS    (SM_B + NSTAGE * B_STAGE_BYTES)       // 98304
#define SM_VAS   (SM_QS + 512)
#define SM_ES    (SM_VAS + 512)
#define SM_PS    (SM_ES + 512)
#define SM_RED   (SM_PS + 512)
#define SM_CST   (SM_RED + 128)                        // 1 partial ctx slice
#define SM_TOTAL (SM_CST + 2048)                       // ~100.5 KB -> 2 CTAs/SM

// ---------------- device scratch ----------------
__device__ float g_p[NB * LL];
__device__ float g_pz[NCTAS];
__device__ float g_pc[(size_t)NCTAS * QK];
__device__ int   g_cnt[NB];                 // zero-init; self-resetting

// ---------------- helpers ----------------
__device__ __forceinline__ void cp16(uint32_t smem_addr, const float* src) {
    asm volatile("cp.async.cg.shared.global [%0], [%1], 16;\n" :: "r"(smem_addr), "l"(src));
}
__device__ __forceinline__ void cp_commit() { asm volatile("cp.async.commit_group;\n"); }
__device__ __forceinline__ void cp_wait1()  { asm volatile("cp.async.wait_group 1;\n"); }
__device__ __forceinline__ void cp_wait0()  { asm volatile("cp.async.wait_group 0;\n"); }

__device__ __forceinline__ void mma_tf32(float* c, const uint32_t* a, const uint32_t* b) {
    asm volatile(
        "mma.sync.aligned.m16n8k8.row.col.f32.tf32.tf32.f32 "
        "{%0,%1,%2,%3},{%4,%5,%6,%7},{%8,%9},{%0,%1,%2,%3};"
        : "+f"(c[0]), "+f"(c[1]), "+f"(c[2]), "+f"(c[3])
        : "r"(a[0]), "r"(a[1]), "r"(a[2]), "r"(a[3]), "r"(b[0]), "r"(b[1]));
}
__device__ __forceinline__ float tanh_fast(float x) {
    float y; asm("tanh.approx.f32 %0, %1;" : "=f"(y) : "f"(x)); return y;
}

// ---------------- single fused kernel, 2 CTAs/SM ----------------
__global__ void __launch_bounds__(THREADS, 2)
k_fused(const float* __restrict__ X,            // (NB,LL,QK)
        const float* __restrict__ Ua,           // (HH,QK)
        const float* __restrict__ va,           // (1,HH)
        const float* __restrict__ last_hidden,  // (NB,1,QK)
        const float* __restrict__ Wa,           // (HH,QK)
        float* __restrict__ out) {
    extern __shared__ char sm[];
    const uint32_t smem_u32 = (uint32_t)__cvta_generic_to_shared(sm);
    float* qs  = reinterpret_cast<float*>(sm + SM_QS);
    float* vas = reinterpret_cast<float*>(sm + SM_VAS);
    float* es  = reinterpret_cast<float*>(sm + SM_ES);
    float* ps  = reinterpret_cast<float*>(sm + SM_PS);
    float* red = reinterpret_cast<float*>(sm + SM_RED);
    float* cst = reinterpret_cast<float*>(sm + SM_CST);
    __shared__ int s_last;

    const int tid  = threadIdx.x;
    const int bx   = blockIdx.x;
    const int row0 = bx * ROWS_PER_CTA;
    const int n    = row0 >> 11;              // row0 / 2048

    const int warp = tid >> 5;
    const int lane = tid & 31;
    const int wr = warp >> 2;          // 0..1 : 64-row strip
    const int wc = warp & 3;           // 0..3 : 32-col strip
    const int g  = lane >> 2;
    const int t  = lane & 3;
    const int xm = g << 4;             // swizzle xor for fragment loads

    if (tid < ROWS_PER_CTA) es[tid] = 0.f;
    if (tid < HH) vas[tid] = va[tid];

    // ---- chunk loader: cp.async into XOR-swizzled 128B rows ----
    auto load_chunk = [&](int kc, int stage) {
        const uint32_t abase = smem_u32 + SM_A + stage * A_STAGE_BYTES;
        const uint32_t bbase = smem_u32 + SM_B + stage * B_STAGE_BYTES;
        const float* Xs  = X  + (size_t)row0 * QK + kc * KCHUNK;
        const float* Uas = Ua + kc * KCHUNK;
#pragma unroll
        for (int i = 0; i < 4; ++i) {                  // A: 1024 x 16B
            int v = tid + i * THREADS;
            int r = v >> 3, s = v & 7;
            cp16(abase + (uint32_t)(r * 128 + ((s * 16) ^ ((r & 7) << 4))),
                 Xs + (size_t)r * QK + s * 4);
        }
#pragma unroll
        for (int i = 0; i < 4; ++i) {                  // B: 1024 x 16B
            int v = tid + i * THREADS;
            int r = v >> 3, s = v & 7;
            cp16(bbase + (uint32_t)(r * 128 + ((s * 16) ^ ((r & 7) << 4))),
                 Uas + (size_t)r * QK + s * 4);
        }
    };

    // prologue: 2 chunks in flight (distance-2, 3 stages)
    load_chunk(0, 0); cp_commit();
    load_chunk(1, 1); cp_commit();

    // ---- q projection, coalesced: each warp does 16 rows ----
    {
        const float4* x4 = reinterpret_cast<const float4*>(last_hidden + (size_t)n * QK);
        float4 xv[4];
#pragma unroll
        for (int k = 0; k < 4; ++k) xv[k] = x4[lane + k * 32];
#pragma unroll
        for (int rr = 0; rr < 16; ++rr) {
            const int h = warp * 16 + rr;
            const float4* w4 = reinterpret_cast<const float4*>(Wa + (size_t)h * QK);
            float a = 0.f;
#pragma unroll
            for (int k = 0; k < 4; ++k) {
                float4 w = w4[lane + k * 32];
                a += w.x * xv[k].x + w.y * xv[k].y + w.z * xv[k].z + w.w * xv[k].w;
            }
#pragma unroll
            for (int o = 16; o > 0; o >>= 1) a += __shfl_xor_sync(0xffffffffu, a, o);
            if (lane == 0) qs[h] = a;
        }
    }

    float acc[2][4][4];   // per warp: 32-row pairs x 4 col-tiles (tile 64x32 via m loop of 4 below)
    float acc2[2][4][4];
#pragma unroll
    for (int m = 0; m < 2; ++m)
#pragma unroll
        for (int j = 0; j < 4; ++j)
#pragma unroll
            for (int c = 0; c < 4; ++c) { acc[m][j][c] = 0.f; acc2[m][j][c] = 0.f; }

    // ---- mainloop: 3-stage, distance-2 prefetch ----
#pragma unroll 1
    for (int kc = 0; kc < NCHUNKS; ++kc) {
        if (kc < NCHUNKS - 1) cp_wait1();   // chunk kc resident (kc+1 may be in flight)
        else                  cp_wait0();
        __syncthreads();

        int stage = kc - (kc / NSTAGE) * NSTAGE;     // kc % 3
        const char* Ab = sm + SM_A + stage * A_STAGE_BYTES;
        const char* Bb = sm + SM_B + stage * B_STAGE_BYTES;

#pragma unroll
        for (int ks = 0; ks < 4; ++ks) {
            const int k0 = ks * 8;
            const int cb0 = ((k0 + t) * 4) ^ xm;
            const int cb1 = ((k0 + t + 4) * 4) ^ xm;
            uint32_t bu[4][2];
#pragma unroll
            for (int j = 0; j < 4; ++j) {
                const char* br = Bb + (wc * 32 + j * 8 + g) * 128;
                bu[j][0] = *reinterpret_cast<const uint32_t*>(br + cb0);
                bu[j][1] = *reinterpret_cast<const uint32_t*>(br + cb1);
            }
#pragma unroll
            for (int m = 0; m < 4; ++m) {
                const char* ar0 = Ab + (wr * 64 + m * 16 + g) * 128;
                const char* ar1 = ar0 + 8 * 128;
                uint32_t au[4];
                au[0] = *reinterpret_cast<const uint32_t*>(ar0 + cb0);
                au[1] = *reinterpret_cast<const uint32_t*>(ar1 + cb0);
                au[2] = *reinterpret_cast<const uint32_t*>(ar0 + cb1);
                au[3] = *reinterpret_cast<const uint32_t*>(ar1 + cb1);
                float* am0 = (m < 2) ? acc[m][0] : acc2[m - 2][0];
#pragma unroll
                for (int j = 0; j < 4; ++j) {
                    float* cj = ((m < 2) ? acc[m][j] : acc2[m - 2][j]);
                    mma_tf32(cj, au, bu[j]);
                }
                (void)am0;
            }
            // prefetch chunk kc+2 into stage (kc+2)%3 == (kc-1)%3 (freed at this barrier)
            if (ks == 0 && kc + 2 < NCHUNKS) {
                int ns = stage + 2; if (ns >= NSTAGE) ns -= NSTAGE;
                load_chunk(kc + 2, ns);
                cp_commit();
            }
        }
    }

    // ---- epilogue: e_r = sum_h va[h] * tanh(q[h] + C[r,h]) ----
#pragma unroll
    for (int m = 0; m < 4; ++m) {
#pragma unroll
        for (int rr = 0; rr < 2; ++rr) {
            float pa = 0.f;
#pragma unroll
            for (int j = 0; j < 4; ++j) {
#pragma unroll
                for (int cc = 0; cc < 2; ++cc) {
                    int h = wc * 32 + j * 8 + t * 2 + cc;
                    float cacc = (m < 2) ? acc[m][j][rr * 2 + cc] : acc2[m - 2][j][rr * 2 + cc];
                    pa += vas[h] * tanh_fast(qs[h] + cacc);
                }
            }
            pa += __shfl_xor_sync(0xffffffffu, pa, 1);
            pa += __shfl_xor_sync(0xffffffffu, pa, 2);
            if (t == 0) atomicAdd(&es[wr * 64 + m * 16 + rr * 8 + g], pa);
        }
    }
    __syncthreads();

    // energies bounded (|e| <= sum|va| ~= 11): exp without max-pass is safe
    if (tid < ROWS_PER_CTA) {
        float p = __expf(es[tid]);
        ps[tid] = p;
        g_p[row0 + tid] = p;
        float s = p;
#pragma unroll
        for (int o = 16; o > 0; o >>= 1) s += __shfl_xor_sync(0xffffffffu, s, o);
        if (lane == 0) red[warp] = s;
    }
    __syncthreads();
    if (tid == 0) {
        float Z = 0.f;
#pragma unroll
        for (int i = 0; i < 4; ++i) Z += red[i];
        g_pz[bx] = Z;
    }
    __syncthreads();   // ps[] visible

    // ---- partial context: 2 row-halves of 64, then smem combine ----
    {
        const int c4 = (tid & 127) * 4;
        const int half = tid >> 7;               // 0 or 1
        const float* Xp = X + (size_t)(row0 + half * 64) * QK + c4;
        float4 a = make_float4(0.f, 0.f, 0.f, 0.f);
#pragma unroll 4
        for (int l = 0; l < 64; ++l) {
            float pl = ps[half * 64 + l];
            float4 x = *reinterpret_cast<const float4*>(Xp + (size_t)l * QK);
            a.x += pl * x.x; a.y += pl * x.y; a.z += pl * x.z; a.w += pl * x.w;
        }
        if (half == 1) *reinterpret_cast<float4*>(cst + c4) = a;
        __syncthreads();
        if (half == 0) {
            float4 b = *reinterpret_cast<const float4*>(cst + c4);
            a.x += b.x; a.y += b.y; a.z += b.z; a.w += b.w;
            *reinterpret_cast<float4*>(&g_pc[(size_t)bx * QK + c4]) = a;
        }
    }

    // ---- fan-in: last CTA of the batch combines ----
    __syncthreads();
    if (tid == 0) {
        __threadfence();
        int old = atomicAdd(&g_cnt[n], 1);
        s_last = (old == SPLITS - 1) ? 1 : 0;
    }
    __syncthreads();
    if (s_last) {
        __threadfence();
        float Z = 0.f;
#pragma unroll
        for (int i = 0; i < SPLITS; ++i) Z += g_pz[n * SPLITS + i];
        const float rZ = 1.f / Z;

        float* ctx = out;                       // (NB, QK)
        float* wts = out + (size_t)NB * QK;     // (NB, LL)
#pragma unroll
        for (int dd = 0; dd < QK / THREADS; ++dd) {
            int d = tid + dd * THREADS;
            float c = 0.f;
#pragma unroll
            for (int i = 0; i < SPLITS; ++i)
                c += g_pc[(size_t)(n * SPLITS + i) * QK + d];
            ctx[(size_t)n * QK + d] = c * rZ;
        }
#pragma unroll
        for (int i = 0; i < LL / THREADS; ++i) {
            int l = tid + i * THREADS;
            wts[(size_t)n * LL + l] = g_p[(size_t)n * LL + l] * rZ;
        }
        if (tid == 0) g_cnt[n] = 0;   // self-reset for next replay
    }
}

// ---------------- launch ----------------
extern "C" void kernel_launch(void* const* d_in, const int* in_sizes, int n_in,
                              void* d_out, int out_size) {
    const float* last_hidden     = (const float*)d_in[0];
    const float* encoder_outputs = (const float*)d_in[1];
    const float* Wa              = (const float*)d_in[2];
    const float* Ua              = (const float*)d_in[3];
    const float* va              = (const float*)d_in[4];
    float* out = (float*)d_out;

    static bool attr_set = false;
    if (!attr_set) {
        cudaFuncSetAttribute(k_fused, cudaFuncAttributeMaxDynamicSharedMemorySize, SM_TOTAL);
        attr_set = true;
    }

    k_fused<<<NCTAS, THREADS, SM_TOTAL>>>(encoder_outputs, Ua, va, last_hidden, Wa, out);
}

// round 7
// speedup vs baseline: 1.6727x; 1.1296x over previous
#include <cuda_runtime.h>
#include <cuda_bf16.h>
#include <cstdint>

// Problem dims (fixed)
#define NB   256
#define LL   2048
#define QK   512
#define HH   128

#define ROWS_PER_CTA 128
#define SPLITS       (LL / ROWS_PER_CTA)    // 16
#define NCTAS        (NB * SPLITS)          // 4096
#define KCHUNK       32                     // floats -> 128B rows
#define NCHUNKS      (QK / KCHUNK)          // 16
#define THREADS      256
#define NSTAGE       3

#define A_STAGE_BYTES (ROWS_PER_CTA * 128)  // 16384
#define B_STAGE_BYTES (HH * 128)            // 16384

// smem byte offsets
#define SM_A     0
#define SM_B     (NSTAGE * A_STAGE_BYTES)              // 49152
#define SM_QS    (SM_B + NSTAGE * B_STAGE_BYTES)       // 98304
#define SM_VAS   (SM_QS + 512)
#define SM_ES    (SM_VAS + 512)
#define SM_PS    (SM_ES + 512)
#define SM_RED   (SM_PS + 512)
#define SM_CST   (SM_RED + 128)                        // 1 partial ctx slice
#define SM_TOTAL (SM_CST + 2048)                       // ~100.5 KB -> 2 CTAs/SM

// ---------------- device scratch ----------------
__device__ float g_q[NB * HH];              // q = Wa @ last_hidden
__device__ float g_p[NB * LL];
__device__ float g_pz[NCTAS];
__device__ float g_pc[(size_t)NCTAS * QK];
__device__ int   g_cnt[NB];                 // zero-init; self-resetting

// ---------------- helpers ----------------
__device__ __forceinline__ void cp16(uint32_t smem_addr, const float* src) {
    asm volatile("cp.async.cg.shared.global [%0], [%1], 16;\n" :: "r"(smem_addr), "l"(src));
}
__device__ __forceinline__ void cp_commit() { asm volatile("cp.async.commit_group;\n"); }
__device__ __forceinline__ void cp_wait1()  { asm volatile("cp.async.wait_group 1;\n"); }
__device__ __forceinline__ void cp_wait0()  { asm volatile("cp.async.wait_group 0;\n"); }

__device__ __forceinline__ void mma_tf32(float* c, const uint32_t* a, const uint32_t* b) {
    asm volatile(
        "mma.sync.aligned.m16n8k8.row.col.f32.tf32.tf32.f32 "
        "{%0,%1,%2,%3},{%4,%5,%6,%7},{%8,%9},{%0,%1,%2,%3};"
        : "+f"(c[0]), "+f"(c[1]), "+f"(c[2]), "+f"(c[3])
        : "r"(a[0]), "r"(a[1]), "r"(a[2]), "r"(a[3]), "r"(b[0]), "r"(b[1]));
}
__device__ __forceinline__ float tanh_fast(float x) {
    float y; asm("tanh.approx.f32 %0, %1;" : "=f"(y) : "f"(x)); return y;
}

// ---------------- kernel 0: q projection (coalesced, warp-per-rows) ----------------
// grid = NB, block = 512 (16 warps); each warp computes 8 rows of q[n,:]
__global__ void __launch_bounds__(512)
k_qproj(const float* __restrict__ last_hidden, const float* __restrict__ Wa) {
    const int n    = blockIdx.x;
    const int warp = threadIdx.x >> 5;
    const int lane = threadIdx.x & 31;

    const float4* x4 = reinterpret_cast<const float4*>(last_hidden + (size_t)n * QK);
    float4 xv[4];
#pragma unroll
    for (int k = 0; k < 4; ++k) xv[k] = x4[lane + k * 32];

#pragma unroll
    for (int rr = 0; rr < 8; ++rr) {
        const int h = warp * 8 + rr;
        const float4* w4 = reinterpret_cast<const float4*>(Wa + (size_t)h * QK);
        float a = 0.f;
#pragma unroll
        for (int k = 0; k < 4; ++k) {
            float4 w = w4[lane + k * 32];
            a += w.x * xv[k].x + w.y * xv[k].y + w.z * xv[k].z + w.w * xv[k].w;
        }
#pragma unroll
        for (int o = 16; o > 0; o >>= 1) a += __shfl_xor_sync(0xffffffffu, a, o);
        if (lane == 0) g_q[n * HH + h] = a;
    }
}

// ---------------- kernel 1: fused energies + softmax + partial context, 2 CTAs/SM ----------------
__global__ void __launch_bounds__(THREADS, 2)
k_fused(const float* __restrict__ X,            // (NB,LL,QK)
        const float* __restrict__ Ua,           // (HH,QK)
        const float* __restrict__ va,           // (1,HH)
        float* __restrict__ out) {
    extern __shared__ char sm[];
    const uint32_t smem_u32 = (uint32_t)__cvta_generic_to_shared(sm);
    float* qs  = reinterpret_cast<float*>(sm + SM_QS);
    float* vas = reinterpret_cast<float*>(sm + SM_VAS);
    float* es  = reinterpret_cast<float*>(sm + SM_ES);
    float* ps  = reinterpret_cast<float*>(sm + SM_PS);
    float* red = reinterpret_cast<float*>(sm + SM_RED);
    float* cst = reinterpret_cast<float*>(sm + SM_CST);
    __shared__ int s_last;

    const int tid  = threadIdx.x;
    const int bx   = blockIdx.x;
    const int row0 = bx * ROWS_PER_CTA;
    const int n    = row0 >> 11;              // row0 / 2048

    const int warp = tid >> 5;
    const int lane = tid & 31;
    const int wr = warp >> 2;          // 0..1 : 64-row strip
    const int wc = warp & 3;           // 0..3 : 32-col strip
    const int g  = lane >> 2;
    const int t  = lane & 3;
    const int xm = g << 4;             // swizzle xor for fragment loads

    if (tid < ROWS_PER_CTA) es[tid] = 0.f;
    if (tid < HH) {
        vas[tid] = va[tid];
        qs[tid]  = g_q[n * HH + tid];
    }

    // ---- chunk loader: cp.async into XOR-swizzled 128B rows ----
    auto load_chunk = [&](int kc, int stage) {
        const uint32_t abase = smem_u32 + SM_A + stage * A_STAGE_BYTES;
        const uint32_t bbase = smem_u32 + SM_B + stage * B_STAGE_BYTES;
        const float* Xs  = X  + (size_t)row0 * QK + kc * KCHUNK;
        const float* Uas = Ua + kc * KCHUNK;
#pragma unroll
        for (int i = 0; i < 4; ++i) {                  // A: 1024 x 16B
            int v = tid + i * THREADS;
            int r = v >> 3, s = v & 7;
            cp16(abase + (uint32_t)(r * 128 + ((s * 16) ^ ((r & 7) << 4))),
                 Xs + (size_t)r * QK + s * 4);
        }
#pragma unroll
        for (int i = 0; i < 4; ++i) {                  // B: 1024 x 16B
            int v = tid + i * THREADS;
            int r = v >> 3, s = v & 7;
            cp16(bbase + (uint32_t)(r * 128 + ((s * 16) ^ ((r & 7) << 4))),
                 Uas + (size_t)r * QK + s * 4);
        }
    };

    // prologue: 2 chunks in flight (distance-2, 3 stages)
    load_chunk(0, 0); cp_commit();
    load_chunk(1, 1); cp_commit();

    float acc[4][4][4];
#pragma unroll
    for (int m = 0; m < 4; ++m)
#pragma unroll
        for (int j = 0; j < 4; ++j)
#pragma unroll
            for (int c = 0; c < 4; ++c) acc[m][j][c] = 0.f;

    // ---- mainloop: 3-stage, distance-2 prefetch ----
#pragma unroll 1
    for (int kc = 0; kc < NCHUNKS; ++kc) {
        if (kc < NCHUNKS - 1) cp_wait1();   // chunk kc resident (kc+1 may be in flight)
        else                  cp_wait0();
        __syncthreads();

        int stage = kc - (kc / NSTAGE) * NSTAGE;     // kc % 3
        const char* Ab = sm + SM_A + stage * A_STAGE_BYTES;
        const char* Bb = sm + SM_B + stage * B_STAGE_BYTES;

#pragma unroll
        for (int ks = 0; ks < 4; ++ks) {
            const int k0 = ks * 8;
            const int cb0 = ((k0 + t) * 4) ^ xm;
            const int cb1 = ((k0 + t + 4) * 4) ^ xm;
            uint32_t bu[4][2];
#pragma unroll
            for (int j = 0; j < 4; ++j) {
                const char* br = Bb + (wc * 32 + j * 8 + g) * 128;
                bu[j][0] = *reinterpret_cast<const uint32_t*>(br + cb0);
                bu[j][1] = *reinterpret_cast<const uint32_t*>(br + cb1);
            }
#pragma unroll
            for (int m = 0; m < 4; ++m) {
                const char* ar0 = Ab + (wr * 64 + m * 16 + g) * 128;
                const char* ar1 = ar0 + 8 * 128;
                uint32_t au[4];
                au[0] = *reinterpret_cast<const uint32_t*>(ar0 + cb0);
                au[1] = *reinterpret_cast<const uint32_t*>(ar1 + cb0);
                au[2] = *reinterpret_cast<const uint32_t*>(ar0 + cb1);
                au[3] = *reinterpret_cast<const uint32_t*>(ar1 + cb1);
#pragma unroll
                for (int j = 0; j < 4; ++j) mma_tf32(acc[m][j], au, bu[j]);
            }
            // prefetch chunk kc+2 into stage (kc+2)%3 == (kc-1)%3 (freed at this barrier)
            if (ks == 0 && kc + 2 < NCHUNKS) {
                int ns = stage + 2; if (ns >= NSTAGE) ns -= NSTAGE;
                load_chunk(kc + 2, ns);
                cp_commit();
            }
        }
    }

    // ---- epilogue: e_r = sum_h va[h] * tanh(q[h] + C[r,h]) ----
#pragma unroll
    for (int m = 0; m < 4; ++m) {
#pragma unroll
        for (int rr = 0; rr < 2; ++rr) {
            float pa = 0.f;
#pragma unroll
            for (int j = 0; j < 4; ++j) {
#pragma unroll
                for (int cc = 0; cc < 2; ++cc) {
                    int h = wc * 32 + j * 8 + t * 2 + cc;
                    pa += vas[h] * tanh_fast(qs[h] + acc[m][j][rr * 2 + cc]);
                }
            }
            pa += __shfl_xor_sync(0xffffffffu, pa, 1);
            pa += __shfl_xor_sync(0xffffffffu, pa, 2);
            if (t == 0) atomicAdd(&es[wr * 64 + m * 16 + rr * 8 + g], pa);
        }
    }
    __syncthreads();

    // energies bounded (|e| <= sum|va| ~= 11): exp without max-pass is safe
    if (tid < ROWS_PER_CTA) {
        float p = __expf(es[tid]);
        ps[tid] = p;
        g_p[row0 + tid] = p;
        float s = p;
#pragma unroll
        for (int o = 16; o > 0; o >>= 1) s += __shfl_xor_sync(0xffffffffu, s, o);
        if (lane == 0) red[warp] = s;
    }
    __syncthreads();
    if (tid == 0) {
        float Z = 0.f;
#pragma unroll
        for (int i = 0; i < 4; ++i) Z += red[i];
        g_pz[bx] = Z;
    }
    __syncthreads();   // ps[] visible

    // ---- partial context: 2 row-halves of 64, then smem combine ----
    {
        const int c4 = (tid & 127) * 4;
        const int half = tid >> 7;               // 0 or 1
        const float* Xp = X + (size_t)(row0 + half * 64) * QK + c4;
        float4 a = make_float4(0.f, 0.f, 0.f, 0.f);
#pragma unroll 8
        for (int l = 0; l < 64; ++l) {
            float pl = ps[half * 64 + l];
            float4 x = *reinterpret_cast<const float4*>(Xp + (size_t)l * QK);
            a.x += pl * x.x; a.y += pl * x.y; a.z += pl * x.z; a.w += pl * x.w;
        }
        if (half == 1) *reinterpret_cast<float4*>(cst + c4) = a;
        __syncthreads();
        if (half == 0) {
            float4 b = *reinterpret_cast<const float4*>(cst + c4);
            a.x += b.x; a.y += b.y; a.z += b.z; a.w += b.w;
            *reinterpret_cast<float4*>(&g_pc[(size_t)bx * QK + c4]) = a;
        }
    }

    // ---- fan-in: last CTA of the batch combines ----
    __syncthreads();
    if (tid == 0) {
        __threadfence();
        int old = atomicAdd(&g_cnt[n], 1);
        s_last = (old == SPLITS - 1) ? 1 : 0;
    }
    __syncthreads();
    if (s_last) {
        __threadfence();
        float Z = 0.f;
#pragma unroll
        for (int i = 0; i < SPLITS; ++i) Z += g_pz[n * SPLITS + i];
        const float rZ = 1.f / Z;

        float* ctx = out;                       // (NB, QK)
        float* wts = out + (size_t)NB * QK;     // (NB, LL)
#pragma unroll
        for (int dd = 0; dd < QK / THREADS; ++dd) {
            int d = tid + dd * THREADS;
            float c = 0.f;
#pragma unroll
            for (int i = 0; i < SPLITS; ++i)
                c += g_pc[(size_t)(n * SPLITS + i) * QK + d];
            ctx[(size_t)n * QK + d] = c * rZ;
        }
#pragma unroll
        for (int i = 0; i < LL / THREADS; ++i) {
            int l = tid + i * THREADS;
            wts[(size_t)n * LL + l] = g_p[(size_t)n * LL + l] * rZ;
        }
        if (tid == 0) g_cnt[n] = 0;   // self-reset for next replay
    }
}

// ---------------- launch ----------------
extern "C" void kernel_launch(void* const* d_in, const int* in_sizes, int n_in,
                              void* d_out, int out_size) {
    const float* last_hidden     = (const float*)d_in[0];
    const float* encoder_outputs = (const float*)d_in[1];
    const float* Wa              = (const float*)d_in[2];
    const float* Ua              = (const float*)d_in[3];
    const float* va              = (const float*)d_in[4];
    float* out = (float*)d_out;

    static bool attr_set = false;
    if (!attr_set) {
        cudaFuncSetAttribute(k_fused, cudaFuncAttributeMaxDynamicSharedMemorySize, SM_TOTAL);
        attr_set = true;
    }

    k_qproj<<<NB, 512>>>(last_hidden, Wa);
    k_fused<<<NCTAS, THREADS, SM_TOTAL>>>(encoder_outputs, Ua, va, out);
}

// round 8
// speedup vs baseline: 1.7847x; 1.0670x over previous
#include <cuda_runtime.h>
#include <cuda_bf16.h>
#include <cstdint>

// Problem dims (fixed)
#define NB   256
#define LL   2048
#define QK   512
#define HH   128

#define ROWS_PER_CTA 128
#define SPLITS       (LL / ROWS_PER_CTA)    // 16
#define NCTAS        (NB * SPLITS)          // 4096
#define KCHUNK       32                     // floats -> 128B rows
#define NCHUNKS      (QK / KCHUNK)          // 16
#define THREADS      256
#define NSTAGE       3

#define A_STAGE_BYTES (ROWS_PER_CTA * 128)  // 16384
#define B_STAGE_BYTES (HH * 128)            // 16384

// smem byte offsets
#define SM_A     0
#define SM_B     (NSTAGE * A_STAGE_BYTES)              // 49152
#define SM_QS    (SM_B + NSTAGE * B_STAGE_BYTES)       // 98304
#define SM_VAS   (SM_QS + 512)
#define SM_ES    (SM_VAS + 512)
#define SM_PS    (SM_ES + 512)
#define SM_RED   (SM_PS + 512)
#define SM_CST   (SM_RED + 128)                        // 1 partial ctx slice
#define SM_TOTAL (SM_CST + 2048)                       // ~100.5 KB -> 2 CTAs/SM

// ---------------- device scratch ----------------
__device__ float g_q[NB * HH];              // q = Wa @ last_hidden
__device__ float g_p[NB * LL];
__device__ float g_pz[NCTAS];
__device__ float g_pc[(size_t)NCTAS * QK];
__device__ int   g_cnt[NB];                 // zero-init; self-resetting

// ---------------- helpers ----------------
__device__ __forceinline__ void cp16(uint32_t smem_addr, const float* src) {
    asm volatile("cp.async.cg.shared.global [%0], [%1], 16;\n" :: "r"(smem_addr), "l"(src));
}
__device__ __forceinline__ void cp_commit() { asm volatile("cp.async.commit_group;\n"); }
__device__ __forceinline__ void cp_wait1()  { asm volatile("cp.async.wait_group 1;\n"); }
__device__ __forceinline__ void cp_wait0()  { asm volatile("cp.async.wait_group 0;\n"); }

__device__ __forceinline__ void mma_tf32(float* c, const uint32_t* a, const uint32_t* b) {
    asm volatile(
        "mma.sync.aligned.m16n8k8.row.col.f32.tf32.tf32.f32 "
        "{%0,%1,%2,%3},{%4,%5,%6,%7},{%8,%9},{%0,%1,%2,%3};"
        : "+f"(c[0]), "+f"(c[1]), "+f"(c[2]), "+f"(c[3])
        : "r"(a[0]), "r"(a[1]), "r"(a[2]), "r"(a[3]), "r"(b[0]), "r"(b[1]));
}
__device__ __forceinline__ void ldsm_x4(uint32_t& r0, uint32_t& r1, uint32_t& r2, uint32_t& r3,
                                        uint32_t addr) {
    asm volatile("ldmatrix.sync.aligned.m8n8.x4.shared.b16 {%0,%1,%2,%3}, [%4];"
                 : "=r"(r0), "=r"(r1), "=r"(r2), "=r"(r3) : "r"(addr));
}
__device__ __forceinline__ float tanh_fast(float x) {
    float y; asm("tanh.approx.f32 %0, %1;" : "=f"(y) : "f"(x)); return y;
}

// ---------------- kernel 0: q projection (coalesced, warp-per-rows) ----------------
__global__ void __launch_bounds__(512)
k_qproj(const float* __restrict__ last_hidden, const float* __restrict__ Wa) {
    const int n    = blockIdx.x;
    const int warp = threadIdx.x >> 5;
    const int lane = threadIdx.x & 31;

    const float4* x4 = reinterpret_cast<const float4*>(last_hidden + (size_t)n * QK);
    float4 xv[4];
#pragma unroll
    for (int k = 0; k < 4; ++k) xv[k] = x4[lane + k * 32];

#pragma unroll
    for (int rr = 0; rr < 8; ++rr) {
        const int h = warp * 8 + rr;
        const float4* w4 = reinterpret_cast<const float4*>(Wa + (size_t)h * QK);
        float a = 0.f;
#pragma unroll
        for (int k = 0; k < 4; ++k) {
            float4 w = w4[lane + k * 32];
            a += w.x * xv[k].x + w.y * xv[k].y + w.z * xv[k].z + w.w * xv[k].w;
        }
#pragma unroll
        for (int o = 16; o > 0; o >>= 1) a += __shfl_xor_sync(0xffffffffu, a, o);
        if (lane == 0) g_q[n * HH + h] = a;
    }
}

// ---------------- kernel 1: fused energies + softmax + partial context, 2 CTAs/SM ----------------
__global__ void __launch_bounds__(THREADS, 2)
k_fused(const float* __restrict__ X,            // (NB,LL,QK)
        const float* __restrict__ Ua,           // (HH,QK)
        const float* __restrict__ va,           // (1,HH)
        float* __restrict__ out) {
    extern __shared__ char sm[];
    const uint32_t smem_u32 = (uint32_t)__cvta_generic_to_shared(sm);
    float* qs  = reinterpret_cast<float*>(sm + SM_QS);
    float* vas = reinterpret_cast<float*>(sm + SM_VAS);
    float* es  = reinterpret_cast<float*>(sm + SM_ES);
    float* ps  = reinterpret_cast<float*>(sm + SM_PS);
    float* red = reinterpret_cast<float*>(sm + SM_RED);
    float* cst = reinterpret_cast<float*>(sm + SM_CST);
    __shared__ int s_last;

    const int tid  = threadIdx.x;
    const int bx   = blockIdx.x;
    const int row0 = bx * ROWS_PER_CTA;
    const int n    = row0 >> 11;              // row0 / 2048

    const int warp = tid >> 5;
    const int lane = tid & 31;
    const int wr = warp >> 2;          // 0..1 : 64-row strip
    const int wc = warp & 3;           // 0..3 : 32-col strip
    const int g  = lane >> 2;
    const int t  = lane & 3;

    // ldmatrix per-lane addressing (16B segments, XOR-swizzled rows)
    const int swz  = (lane & 7) << 4;
    const int rowA = lane & 15;                       // A: tile row within 16
    const int hiA  = (lane >> 4) << 4;                // A: 0 or 16 byte-half
    const int rowB = (lane & 7) + ((lane >> 4) << 3); // B: row within 16 (j, j+1 tiles)
    const int hiB  = ((lane >> 3) & 1) << 4;          // B: 0/16 byte-half

    if (tid < ROWS_PER_CTA) es[tid] = 0.f;
    if (tid < HH) {
        vas[tid] = va[tid];
        qs[tid]  = g_q[n * HH + tid];
    }

    // ---- chunk loader: cp.async into XOR-swizzled 128B rows ----
    auto load_chunk = [&](int kc, int stage) {
        const uint32_t abase = smem_u32 + SM_A + stage * A_STAGE_BYTES;
        const uint32_t bbase = smem_u32 + SM_B + stage * B_STAGE_BYTES;
        const float* Xs  = X  + (size_t)row0 * QK + kc * KCHUNK;
        const float* Uas = Ua + kc * KCHUNK;
#pragma unroll
        for (int i = 0; i < 4; ++i) {                  // A: 1024 x 16B
            int v = tid + i * THREADS;
            int r = v >> 3, s = v & 7;
            cp16(abase + (uint32_t)(r * 128 + ((s * 16) ^ ((r & 7) << 4))),
                 Xs + (size_t)r * QK + s * 4);
        }
#pragma unroll
        for (int i = 0; i < 4; ++i) {                  // B: 1024 x 16B
            int v = tid + i * THREADS;
            int r = v >> 3, s = v & 7;
            cp16(bbase + (uint32_t)(r * 128 + ((s * 16) ^ ((r & 7) << 4))),
                 Uas + (size_t)r * QK + s * 4);
        }
    };

    // prologue: 2 chunks in flight (distance-2, 3 stages)
    load_chunk(0, 0); cp_commit();
    load_chunk(1, 1); cp_commit();

    float acc[4][4][4];
#pragma unroll
    for (int m = 0; m < 4; ++m)
#pragma unroll
        for (int j = 0; j < 4; ++j)
#pragma unroll
            for (int c = 0; c < 4; ++c) acc[m][j][c] = 0.f;

    // per-warp constant tile bases (lane offsets folded per-ks below)
    const uint32_t a_tile_off = (uint32_t)((wr * 64 + rowA) * 128);
    const uint32_t b_tile_off = (uint32_t)((wc * 32 + rowB) * 128);

    // ---- mainloop: 3-stage, distance-2 prefetch, ldmatrix operand feed ----
#pragma unroll 1
    for (int kc = 0; kc < NCHUNKS; ++kc) {
        if (kc < NCHUNKS - 1) cp_wait1();   // chunk kc resident (kc+1 may be in flight)
        else                  cp_wait0();
        __syncthreads();

        int stage = kc - (kc / NSTAGE) * NSTAGE;     // kc % 3
        const uint32_t abase = smem_u32 + SM_A + stage * A_STAGE_BYTES + a_tile_off;
        const uint32_t bbase = smem_u32 + SM_B + stage * B_STAGE_BYTES + b_tile_off;

#pragma unroll
        for (int ks = 0; ks < 4; ++ks) {
            const uint32_t colA = (uint32_t)((ks * 32 + hiA) ^ swz);
            const uint32_t colB = (uint32_t)((ks * 32 + hiB) ^ swz);

            uint32_t bu[4][2];
#pragma unroll
            for (int jj = 0; jj < 2; ++jj) {  // loads j=2jj and j=2jj+1
                ldsm_x4(bu[2*jj][0], bu[2*jj][1], bu[2*jj+1][0], bu[2*jj+1][1],
                        bbase + (uint32_t)(jj * 16 * 128) + colB);
            }
#pragma unroll
            for (int m = 0; m < 4; ++m) {
                uint32_t au[4];
                ldsm_x4(au[0], au[1], au[2], au[3],
                        abase + (uint32_t)(m * 16 * 128) + colA);
#pragma unroll
                for (int j = 0; j < 4; ++j) mma_tf32(acc[m][j], au, bu[j]);
            }
            // prefetch chunk kc+2 into stage (kc+2)%3 == (kc-1)%3 (freed at this barrier)
            if (ks == 0 && kc + 2 < NCHUNKS) {
                int ns = stage + 2; if (ns >= NSTAGE) ns -= NSTAGE;
                load_chunk(kc + 2, ns);
                cp_commit();
            }
        }
    }

    // ---- epilogue: e_r = sum_h va[h] * tanh(q[h] + C[r,h]) ----
#pragma unroll
    for (int m = 0; m < 4; ++m) {
#pragma unroll
        for (int rr = 0; rr < 2; ++rr) {
            float pa = 0.f;
#pragma unroll
            for (int j = 0; j < 4; ++j) {
#pragma unroll
                for (int cc = 0; cc < 2; ++cc) {
                    int h = wc * 32 + j * 8 + t * 2 + cc;
                    pa += vas[h] * tanh_fast(qs[h] + acc[m][j][rr * 2 + cc]);
                }
            }
            pa += __shfl_xor_sync(0xffffffffu, pa, 1);
            pa += __shfl_xor_sync(0xffffffffu, pa, 2);
            if (t == 0) atomicAdd(&es[wr * 64 + m * 16 + rr * 8 + g], pa);
        }
    }
    __syncthreads();

    // energies bounded (|e| <= sum|va| ~= 11): exp without max-pass is safe
    if (tid < ROWS_PER_CTA) {
        float p = __expf(es[tid]);
        ps[tid] = p;
        g_p[row0 + tid] = p;
        float s = p;
#pragma unroll
        for (int o = 16; o > 0; o >>= 1) s += __shfl_xor_sync(0xffffffffu, s, o);
        if (lane == 0) red[warp] = s;
    }
    __syncthreads();
    if (tid == 0) {
        float Z = 0.f;
#pragma unroll
        for (int i = 0; i < 4; ++i) Z += red[i];
        g_pz[bx] = Z;
    }
    __syncthreads();   // ps[] visible

    // ---- partial context: 2 row-halves of 64, then smem combine ----
    {
        const int c4 = (tid & 127) * 4;
        const int half = tid >> 7;               // 0 or 1
        const float* Xp = X + (size_t)(row0 + half * 64) * QK + c4;
        float4 a = make_float4(0.f, 0.f, 0.f, 0.f);
#pragma unroll 8
        for (int l = 0; l < 64; ++l) {
            float pl = ps[half * 64 + l];
            float4 x = *reinterpret_cast<const float4*>(Xp + (size_t)l * QK);
            a.x += pl * x.x; a.y += pl * x.y; a.z += pl * x.z; a.w += pl * x.w;
        }
        if (half == 1) *reinterpret_cast<float4*>(cst + c4) = a;
        __syncthreads();
        if (half == 0) {
            float4 b = *reinterpret_cast<const float4*>(cst + c4);
            a.x += b.x; a.y += b.y; a.z += b.z; a.w += b.w;
            *reinterpret_cast<float4*>(&g_pc[(size_t)bx * QK + c4]) = a;
        }
    }

    // ---- fan-in: last CTA of the batch combines ----
    __syncthreads();
    if (tid == 0) {
        __threadfence();
        int old = atomicAdd(&g_cnt[n], 1);
        s_last = (old == SPLITS - 1) ? 1 : 0;
    }
    __syncthreads();
    if (s_last) {
        __threadfence();
        float Z = 0.f;
#pragma unroll
        for (int i = 0; i < SPLITS; ++i) Z += g_pz[n * SPLITS + i];
        const float rZ = 1.f / Z;

        float* ctx = out;                       // (NB, QK)
        float* wts = out + (size_t)NB * QK;     // (NB, LL)
#pragma unroll
        for (int dd = 0; dd < QK / THREADS; ++dd) {
            int d = tid + dd * THREADS;
            float c = 0.f;
#pragma unroll
            for (int i = 0; i < SPLITS; ++i)
                c += g_pc[(size_t)(n * SPLITS + i) * QK + d];
            ctx[(size_t)n * QK + d] = c * rZ;
        }
#pragma unroll
        for (int i = 0; i < LL / THREADS; ++i) {
            int l = tid + i * THREADS;
            wts[(size_t)n * LL + l] = g_p[(size_t)n * LL + l] * rZ;
        }
        if (tid == 0) g_cnt[n] = 0;   // self-reset for next replay
    }
}

// ---------------- launch ----------------
extern "C" void kernel_launch(void* const* d_in, const int* in_sizes, int n_in,
                              void* d_out, int out_size) {
    const float* last_hidden     = (const float*)d_in[0];
    const float* encoder_outputs = (const float*)d_in[1];
    const float* Wa              = (const float*)d_in[2];
    const float* Ua              = (const float*)d_in[3];
    const float* va              = (const float*)d_in[4];
    float* out = (float*)d_out;

    static bool attr_set = false;
    if (!attr_set) {
        cudaFuncSetAttribute(k_fused, cudaFuncAttributeMaxDynamicSharedMemorySize, SM_TOTAL);
        attr_set = true;
    }

    k_qproj<<<NB, 512>>>(last_hidden, Wa);
    k_fused<<<NCTAS, THREADS, SM_TOTAL>>>(encoder_outputs, Ua, va, out);
}

// round 9
// speedup vs baseline: 2.1700x; 1.2159x over previous
#include <cuda_runtime.h>
#include <cuda.h>
#include <cstdint>

// Problem dims (fixed)
#define NB   256
#define LL   2048
#define QK   512
#define HH   128

#define ROWS_PER_CTA 128
#define SPLITS       (LL / ROWS_PER_CTA)    // 16
#define NCTAS        (NB * SPLITS)          // 4096
#define KCHUNK       32                     // floats -> 128B rows (SW128 atom)
#define NCHUNKS      (QK / KCHUNK)          // 16
#define THREADS      256
#define NSTAGE       3

#define A_STAGE_BYTES 16384                 // 128 rows x 128B
#define B_STAGE_BYTES 16384                 // 128 rows x 128B
#define STAGE_TX      (A_STAGE_BYTES + B_STAGE_BYTES)

// smem byte offsets
#define SM_A     0
#define SM_B     (NSTAGE * A_STAGE_BYTES)              // 49152
#define SM_QS    (SM_B + NSTAGE * B_STAGE_BYTES)       // 98304
#define SM_VAS   (SM_QS + 512)
#define SM_ES    (SM_VAS + 512)
#define SM_PS    (SM_ES + 512)
#define SM_RED   (SM_PS + 512)
#define SM_CST   (SM_RED + 128)                        // 1 partial ctx slice
#define SM_MBAR  (SM_CST + 2048)                       // 3 x 8B mbarriers
#define SM_TOTAL (SM_MBAR + 64)                        // ~100.6 KB -> 2 CTAs/SM

// ---------------- device scratch ----------------
__device__ float g_q[NB * HH];              // q = Wa @ last_hidden
__device__ float g_p[NB * LL];
__device__ float g_pz[NCTAS];
__device__ float g_pc[(size_t)NCTAS * QK];
__device__ int   g_cnt[NB];                 // zero-init; self-resetting

// ---------------- helpers ----------------
__device__ __forceinline__ void mbar_init(uint32_t a, uint32_t cnt) {
    asm volatile("mbarrier.init.shared.b64 [%0], %1;" :: "r"(a), "r"(cnt) : "memory");
}
__device__ __forceinline__ void mbar_expect_tx(uint32_t a, uint32_t bytes) {
    asm volatile("mbarrier.arrive.expect_tx.shared.b64 _, [%0], %1;" :: "r"(a), "r"(bytes) : "memory");
}
__device__ __forceinline__ void mbar_wait(uint32_t a, uint32_t par) {
    asm volatile(
        "{\n\t.reg .pred P1;\n"
        "WAIT_LOOP_%=:\n\t"
        "mbarrier.try_wait.parity.acquire.cta.shared::cta.b64 P1, [%0], %1, 0x989680;\n\t"
        "@P1 bra.uni WAIT_DONE_%=;\n\t"
        "bra.uni WAIT_LOOP_%=;\n"
        "WAIT_DONE_%=:\n\t}"
        :: "r"(a), "r"(par) : "memory");
}
__device__ __forceinline__ void tma2d(uint32_t dst, const CUtensorMap* m, int x, int y, uint32_t bar) {
    asm volatile(
        "cp.async.bulk.tensor.2d.shared::cta.global.tile.mbarrier::complete_tx::bytes "
        "[%0], [%1, {%2, %3}], [%4];"
        :: "r"(dst), "l"(m), "r"(x), "r"(y), "r"(bar) : "memory");
}
__device__ __forceinline__ void mma_tf32(float* c, const uint32_t* a, const uint32_t* b) {
    asm volatile(
        "mma.sync.aligned.m16n8k8.row.col.f32.tf32.tf32.f32 "
        "{%0,%1,%2,%3},{%4,%5,%6,%7},{%8,%9},{%0,%1,%2,%3};"
        : "+f"(c[0]), "+f"(c[1]), "+f"(c[2]), "+f"(c[3])
        : "r"(a[0]), "r"(a[1]), "r"(a[2]), "r"(a[3]), "r"(b[0]), "r"(b[1]));
}
__device__ __forceinline__ void ldsm_x4(uint32_t& r0, uint32_t& r1, uint32_t& r2, uint32_t& r3,
                                        uint32_t addr) {
    asm volatile("ldmatrix.sync.aligned.m8n8.x4.shared.b16 {%0,%1,%2,%3}, [%4];"
                 : "=r"(r0), "=r"(r1), "=r"(r2), "=r"(r3) : "r"(addr));
}
__device__ __forceinline__ float tanh_fast(float x) {
    float y; asm("tanh.approx.f32 %0, %1;" : "=f"(y) : "f"(x)); return y;
}

// ---------------- kernel 0: q projection (coalesced, warp-per-rows) ----------------
__global__ void __launch_bounds__(512)
k_qproj(const float* __restrict__ last_hidden, const float* __restrict__ Wa) {
    const int n    = blockIdx.x;
    const int warp = threadIdx.x >> 5;
    const int lane = threadIdx.x & 31;

    const float4* x4 = reinterpret_cast<const float4*>(last_hidden + (size_t)n * QK);
    float4 xv[4];
#pragma unroll
    for (int k = 0; k < 4; ++k) xv[k] = x4[lane + k * 32];

#pragma unroll
    for (int rr = 0; rr < 8; ++rr) {
        const int h = warp * 8 + rr;
        const float4* w4 = reinterpret_cast<const float4*>(Wa + (size_t)h * QK);
        float a = 0.f;
#pragma unroll
        for (int k = 0; k < 4; ++k) {
            float4 w = w4[lane + k * 32];
            a += w.x * xv[k].x + w.y * xv[k].y + w.z * xv[k].z + w.w * xv[k].w;
        }
#pragma unroll
        for (int o = 16; o > 0; o >>= 1) a += __shfl_xor_sync(0xffffffffu, a, o);
        if (lane == 0) g_q[n * HH + h] = a;
    }
}

// ---------------- kernel 1: TMA-fed fused energies + softmax + partial context ----------------
__global__ void __launch_bounds__(THREADS, 2)
k_fused(const __grid_constant__ CUtensorMap tmA,   // X tiles, SW128
        const __grid_constant__ CUtensorMap tmB,   // Ua tiles, SW128
        const float* __restrict__ X,               // (NB,LL,QK) for context re-read
        const float* __restrict__ va,              // (1,HH)
        float* __restrict__ out) {
    extern __shared__ __align__(1024) char sm[];
    const uint32_t smem_u32 = (uint32_t)__cvta_generic_to_shared(sm);
    float* qs  = reinterpret_cast<float*>(sm + SM_QS);
    float* vas = reinterpret_cast<float*>(sm + SM_VAS);
    float* es  = reinterpret_cast<float*>(sm + SM_ES);
    float* ps  = reinterpret_cast<float*>(sm + SM_PS);
    float* red = reinterpret_cast<float*>(sm + SM_RED);
    float* cst = reinterpret_cast<float*>(sm + SM_CST);
    __shared__ int s_last;

    const int tid  = threadIdx.x;
    const int bx   = blockIdx.x;
    const int row0 = bx * ROWS_PER_CTA;
    const int n    = row0 >> 11;              // row0 / 2048

    const int warp = tid >> 5;
    const int lane = tid & 31;
    const int wr = warp >> 2;          // 0..1 : 64-row strip
    const int wc = warp & 3;           // 0..3 : 32-col strip
    const int g  = lane >> 2;
    const int t  = lane & 3;

    // ldmatrix per-lane addressing (16B segments, SW128-swizzled rows)
    const int swz  = (lane & 7) << 4;
    const int rowA = lane & 15;
    const int hiA  = (lane >> 4) << 4;
    const int rowB = (lane & 7) + ((lane >> 4) << 3);
    const int hiB  = ((lane >> 3) & 1) << 4;

    const uint32_t mb = smem_u32 + SM_MBAR;

    if (tid == 0) {
        mbar_init(mb + 0, 1);
        mbar_init(mb + 8, 1);
        mbar_init(mb + 16, 1);
    }
    if (tid < ROWS_PER_CTA) es[tid] = 0.f;
    if (tid < HH) {
        vas[tid] = va[tid];
        qs[tid]  = g_q[n * HH + tid];
    }
    __syncthreads();   // mbarrier init visible

    // prologue: 2 chunks in flight (distance-2, 3 stages)
    if (tid == 0) {
        mbar_expect_tx(mb + 0, STAGE_TX);
        tma2d(smem_u32 + SM_A, &tmA, 0, row0, mb + 0);
        tma2d(smem_u32 + SM_B, &tmB, 0, 0, mb + 0);
        mbar_expect_tx(mb + 8, STAGE_TX);
        tma2d(smem_u32 + SM_A + A_STAGE_BYTES, &tmA, KCHUNK, row0, mb + 8);
        tma2d(smem_u32 + SM_B + B_STAGE_BYTES, &tmB, KCHUNK, 0, mb + 8);
    }

    float acc[4][4][4];
#pragma unroll
    for (int m = 0; m < 4; ++m)
#pragma unroll
        for (int j = 0; j < 4; ++j)
#pragma unroll
            for (int c = 0; c < 4; ++c) acc[m][j][c] = 0.f;

    const uint32_t a_tile_off = (uint32_t)((wr * 64 + rowA) * 128);
    const uint32_t b_tile_off = (uint32_t)((wc * 32 + rowB) * 128);

    // ---- mainloop: 3-stage, distance-2 TMA prefetch, ldmatrix operand feed ----
#pragma unroll 1
    for (int kc = 0; kc < NCHUNKS; ++kc) {
        int stage = kc - (kc / NSTAGE) * NSTAGE;        // kc % 3
        int phase = (kc / NSTAGE) & 1;
        mbar_wait(mb + stage * 8, (uint32_t)phase);     // chunk kc resident
        __syncthreads();                                // all warps done with chunk kc-1

        // issue chunk kc+2 into stage (kc+2)%3 == (kc-1)%3 (freed at this barrier)
        if (tid == 0 && kc + 2 < NCHUNKS) {
            int ns = stage + 2; if (ns >= NSTAGE) ns -= NSTAGE;
            uint32_t bar = mb + ns * 8;
            mbar_expect_tx(bar, STAGE_TX);
            tma2d(smem_u32 + SM_A + ns * A_STAGE_BYTES, &tmA, (kc + 2) * KCHUNK, row0, bar);
            tma2d(smem_u32 + SM_B + ns * B_STAGE_BYTES, &tmB, (kc + 2) * KCHUNK, 0, bar);
        }

        const uint32_t abase = smem_u32 + SM_A + stage * A_STAGE_BYTES + a_tile_off;
        const uint32_t bbase = smem_u32 + SM_B + stage * B_STAGE_BYTES + b_tile_off;

#pragma unroll
        for (int ks = 0; ks < 4; ++ks) {
            const uint32_t colA = (uint32_t)((ks * 32 + hiA) ^ swz);
            const uint32_t colB = (uint32_t)((ks * 32 + hiB) ^ swz);

            uint32_t bu[4][2];
#pragma unroll
            for (int jj = 0; jj < 2; ++jj) {
                ldsm_x4(bu[2*jj][0], bu[2*jj][1], bu[2*jj+1][0], bu[2*jj+1][1],
                        bbase + (uint32_t)(jj * 16 * 128) + colB);
            }
#pragma unroll
            for (int m = 0; m < 4; ++m) {
                uint32_t au[4];
                ldsm_x4(au[0], au[1], au[2], au[3],
                        abase + (uint32_t)(m * 16 * 128) + colA);
#pragma unroll
                for (int j = 0; j < 4; ++j) mma_tf32(acc[m][j], au, bu[j]);
            }
        }
    }

    // ---- epilogue: e_r = sum_h va[h] * tanh(q[h] + C[r,h]) ----
#pragma unroll
    for (int m = 0; m < 4; ++m) {
#pragma unroll
        for (int rr = 0; rr < 2; ++rr) {
            float pa = 0.f;
#pragma unroll
            for (int j = 0; j < 4; ++j) {
#pragma unroll
                for (int cc = 0; cc < 2; ++cc) {
                    int h = wc * 32 + j * 8 + t * 2 + cc;
                    pa += vas[h] * tanh_fast(qs[h] + acc[m][j][rr * 2 + cc]);
                }
            }
            pa += __shfl_xor_sync(0xffffffffu, pa, 1);
            pa += __shfl_xor_sync(0xffffffffu, pa, 2);
            if (t == 0) atomicAdd(&es[wr * 64 + m * 16 + rr * 8 + g], pa);
        }
    }
    __syncthreads();

    // energies bounded (|e| <= sum|va| ~= 11): exp without max-pass is safe
    if (tid < ROWS_PER_CTA) {
        float p = __expf(es[tid]);
        ps[tid] = p;
        g_p[row0 + tid] = p;
        float s = p;
#pragma unroll
        for (int o = 16; o > 0; o >>= 1) s += __shfl_xor_sync(0xffffffffu, s, o);
        if (lane == 0) red[warp] = s;
    }
    __syncthreads();
    if (tid == 0) {
        float Z = 0.f;
#pragma unroll
        for (int i = 0; i < 4; ++i) Z += red[i];
        g_pz[bx] = Z;
    }
    __syncthreads();   // ps[] visible

    // ---- partial context: 2 row-halves of 64, then smem combine ----
    {
        const int c4 = (tid & 127) * 4;
        const int half = tid >> 7;               // 0 or 1
        const float* Xp = X + (size_t)(row0 + half * 64) * QK + c4;
        float4 a = make_float4(0.f, 0.f, 0.f, 0.f);
#pragma unroll 8
        for (int l = 0; l < 64; ++l) {
            float pl = ps[half * 64 + l];
            float4 x = *reinterpret_cast<const float4*>(Xp + (size_t)l * QK);
            a.x += pl * x.x; a.y += pl * x.y; a.z += pl * x.z; a.w += pl * x.w;
        }
        if (half == 1) *reinterpret_cast<float4*>(cst + c4) = a;
        __syncthreads();
        if (half == 0) {
            float4 b = *reinterpret_cast<const float4*>(cst + c4);
            a.x += b.x; a.y += b.y; a.z += b.z; a.w += b.w;
            *reinterpret_cast<float4*>(&g_pc[(size_t)bx * QK + c4]) = a;
        }
    }

    // ---- fan-in: last CTA of the batch combines ----
    __syncthreads();
    if (tid == 0) {
        __threadfence();
        int old = atomicAdd(&g_cnt[n], 1);
        s_last = (old == SPLITS - 1) ? 1 : 0;
    }
    __syncthreads();
    if (s_last) {
        __threadfence();
        float Z = 0.f;
#pragma unroll
        for (int i = 0; i < SPLITS; ++i) Z += g_pz[n * SPLITS + i];
        const float rZ = 1.f / Z;

        float* ctx = out;                       // (NB, QK)
        float* wts = out + (size_t)NB * QK;     // (NB, LL)
#pragma unroll
        for (int dd = 0; dd < QK / THREADS; ++dd) {
            int d = tid + dd * THREADS;
            float c = 0.f;
#pragma unroll
            for (int i = 0; i < SPLITS; ++i)
                c += g_pc[(size_t)(n * SPLITS + i) * QK + d];
            ctx[(size_t)n * QK + d] = c * rZ;
        }
#pragma unroll
        for (int i = 0; i < LL / THREADS; ++i) {
            int l = tid + i * THREADS;
            wts[(size_t)n * LL + l] = g_p[(size_t)n * LL + l] * rZ;
        }
        if (tid == 0) g_cnt[n] = 0;   // self-reset for next replay
    }
}

// ---------------- host: tensormap encode via runtime entry point (no -lcuda) ----------------
typedef CUresult (*tmap_encode_t)(
    CUtensorMap*, CUtensorMapDataType, cuuint32_t, void*,
    const cuuint64_t*, const cuuint64_t*, const cuuint32_t*, const cuuint32_t*,
    CUtensorMapInterleave, CUtensorMapSwizzle, CUtensorMapL2promotion, CUtensorMapFloatOOBfill);

extern "C" void kernel_launch(void* const* d_in, const int* in_sizes, int n_in,
                              void* d_out, int out_size) {
    const float* last_hidden     = (const float*)d_in[0];
    const float* encoder_outputs = (const float*)d_in[1];
    const float* Wa              = (const float*)d_in[2];
    const float* Ua              = (const float*)d_in[3];
    const float* va              = (const float*)d_in[4];
    float* out = (float*)d_out;

    static tmap_encode_t encode = nullptr;
    static bool attr_set = false;
    if (!attr_set) {
        cudaFuncSetAttribute(k_fused, cudaFuncAttributeMaxDynamicSharedMemorySize, SM_TOTAL);
        cudaDriverEntryPointQueryResult qr;
        void* fp = nullptr;
        cudaGetDriverEntryPoint("cuTensorMapEncodeTiled", &fp, cudaEnableDefault, &qr);
        encode = (tmap_encode_t)fp;
        attr_set = true;
    }

    CUtensorMap tmA, tmB;
    {
        cuuint64_t dims[2]   = {QK, (cuuint64_t)NB * LL};
        cuuint64_t stride[1] = {QK * sizeof(float)};
        cuuint32_t box[2]    = {KCHUNK, ROWS_PER_CTA};
        cuuint32_t elems[2]  = {1, 1};
        encode(&tmA, CU_TENSOR_MAP_DATA_TYPE_FLOAT32, 2, (void*)encoder_outputs,
               dims, stride, box, elems,
               CU_TENSOR_MAP_INTERLEAVE_NONE, CU_TENSOR_MAP_SWIZZLE_128B,
               CU_TENSOR_MAP_L2_PROMOTION_L2_128B, CU_TENSOR_MAP_FLOAT_OOB_FILL_NONE);
    }
    {
        cuuint64_t dims[2]   = {QK, HH};
        cuuint64_t stride[1] = {QK * sizeof(float)};
        cuuint32_t box[2]    = {KCHUNK, HH};
        cuuint32_t elems[2]  = {1, 1};
        encode(&tmB, CU_TENSOR_MAP_DATA_TYPE_FLOAT32, 2, (void*)Ua,
               dims, stride, box, elems,
               CU_TENSOR_MAP_INTERLEAVE_NONE, CU_TENSOR_MAP_SWIZZLE_128B,
               CU_TENSOR_MAP_L2_PROMOTION_L2_128B, CU_TENSOR_MAP_FLOAT_OOB_FILL_NONE);
    }

    k_qproj<<<NB, 512>>>(last_hidden, Wa);
    k_fused<<<NCTAS, THREADS, SM_TOTAL>>>(tmA, tmB, encoder_outputs, va, out);
}

// round 10
// speedup vs baseline: 2.3614x; 1.0882x over previous
#include <cuda_runtime.h>
#include <cuda.h>
#include <cstdint>

// Problem dims (fixed)
#define NB   256
#define LL   2048
#define QK   512
#define HH   128

#define ROWS_PER_CTA 128
#define SPLITS       (LL / ROWS_PER_CTA)    // 16
#define NCTAS        (NB * SPLITS)          // 4096
#define KCHUNK       32                     // floats -> 128B rows (SW128 atom)
#define NCHUNKS      (QK / KCHUNK)          // 16
#define THREADS      256
#define NSTAGE       3

#define A_STAGE_BYTES 16384                 // 128 rows x 128B
#define B_STAGE_BYTES 16384                 // 128 rows x 128B
#define STAGE_TX      (A_STAGE_BYTES + B_STAGE_BYTES)

// smem byte offsets
#define SM_A     0
#define SM_B     (NSTAGE * A_STAGE_BYTES)              // 49152
#define SM_QS    (SM_B + NSTAGE * B_STAGE_BYTES)       // 98304
#define SM_VAS   (SM_QS + 512)                         // 98816
#define SM_ES4   (SM_VAS + 512)                        // 99328: 4 x 128 floats
#define SM_PS    (SM_ES4 + 2048)                       // 101376
#define SM_RED   (SM_PS + 512)                         // 101888
#define SM_CST   (SM_RED + 128)                        // 102016: 1 partial ctx slice
#define SM_MBAR  (SM_CST + 2048)                       // 104064: full[3] + empty[3]
#define SM_TOTAL (SM_MBAR + 64)                        // ~101.7 KB -> 2 CTAs/SM

// ---------------- device scratch ----------------
__device__ float g_q[NB * HH];              // q = Wa @ last_hidden
__device__ float g_p[NB * LL];
__device__ float g_pz[NCTAS];
__device__ float g_pc[(size_t)NCTAS * QK];
__device__ int   g_cnt[NB];                 // zero-init; self-resetting

// ---------------- helpers ----------------
__device__ __forceinline__ void mbar_init(uint32_t a, uint32_t cnt) {
    asm volatile("mbarrier.init.shared.b64 [%0], %1;" :: "r"(a), "r"(cnt) : "memory");
}
__device__ __forceinline__ void mbar_expect_tx(uint32_t a, uint32_t bytes) {
    asm volatile("mbarrier.arrive.expect_tx.shared.b64 _, [%0], %1;" :: "r"(a), "r"(bytes) : "memory");
}
__device__ __forceinline__ void mbar_arrive(uint32_t a) {
    asm volatile("mbarrier.arrive.shared.b64 _, [%0];" :: "r"(a) : "memory");
}
__device__ __forceinline__ void mbar_wait(uint32_t a, uint32_t par) {
    asm volatile(
        "{\n\t.reg .pred P1;\n"
        "WAIT_LOOP_%=:\n\t"
        "mbarrier.try_wait.parity.acquire.cta.shared::cta.b64 P1, [%0], %1, 0x989680;\n\t"
        "@P1 bra.uni WAIT_DONE_%=;\n\t"
        "bra.uni WAIT_LOOP_%=;\n"
        "WAIT_DONE_%=:\n\t}"
        :: "r"(a), "r"(par) : "memory");
}
__device__ __forceinline__ void tma2d(uint32_t dst, const CUtensorMap* m, int x, int y, uint32_t bar) {
    asm volatile(
        "cp.async.bulk.tensor.2d.shared::cta.global.tile.mbarrier::complete_tx::bytes "
        "[%0], [%1, {%2, %3}], [%4];"
        :: "r"(dst), "l"(m), "r"(x), "r"(y), "r"(bar) : "memory");
}
__device__ __forceinline__ void mma_tf32(float* c, const uint32_t* a, const uint32_t* b) {
    asm volatile(
        "mma.sync.aligned.m16n8k8.row.col.f32.tf32.tf32.f32 "
        "{%0,%1,%2,%3},{%4,%5,%6,%7},{%8,%9},{%0,%1,%2,%3};"
        : "+f"(c[0]), "+f"(c[1]), "+f"(c[2]), "+f"(c[3])
        : "r"(a[0]), "r"(a[1]), "r"(a[2]), "r"(a[3]), "r"(b[0]), "r"(b[1]));
}
__device__ __forceinline__ void ldsm_x4(uint32_t& r0, uint32_t& r1, uint32_t& r2, uint32_t& r3,
                                        uint32_t addr) {
    asm volatile("ldmatrix.sync.aligned.m8n8.x4.shared.b16 {%0,%1,%2,%3}, [%4];"
                 : "=r"(r0), "=r"(r1), "=r"(r2), "=r"(r3) : "r"(addr));
}
__device__ __forceinline__ float tanh_fast(float x) {
    float y; asm("tanh.approx.f32 %0, %1;" : "=f"(y) : "f"(x)); return y;
}

// ---------------- kernel 0: q projection (coalesced, warp-per-rows) ----------------
__global__ void __launch_bounds__(512)
k_qproj(const float* __restrict__ last_hidden, const float* __restrict__ Wa) {
    const int n    = blockIdx.x;
    const int warp = threadIdx.x >> 5;
    const int lane = threadIdx.x & 31;

    const float4* x4 = reinterpret_cast<const float4*>(last_hidden + (size_t)n * QK);
    float4 xv[4];
#pragma unroll
    for (int k = 0; k < 4; ++k) xv[k] = x4[lane + k * 32];

#pragma unroll
    for (int rr = 0; rr < 8; ++rr) {
        const int h = warp * 8 + rr;
        const float4* w4 = reinterpret_cast<const float4*>(Wa + (size_t)h * QK);
        float a = 0.f;
#pragma unroll
        for (int k = 0; k < 4; ++k) {
            float4 w = w4[lane + k * 32];
            a += w.x * xv[k].x + w.y * xv[k].y + w.z * xv[k].z + w.w * xv[k].w;
        }
#pragma unroll
        for (int o = 16; o > 0; o >>= 1) a += __shfl_xor_sync(0xffffffffu, a, o);
        if (lane == 0) g_q[n * HH + h] = a;
    }
}

// ---------------- kernel 1: TMA-fed, full/empty-mbarrier fused kernel ----------------
__global__ void __launch_bounds__(THREADS, 2)
k_fused(const __grid_constant__ CUtensorMap tmA,   // X tiles, SW128
        const __grid_constant__ CUtensorMap tmB,   // Ua tiles, SW128
        const float* __restrict__ X,               // (NB,LL,QK) for context re-read
        const float* __restrict__ va,              // (1,HH)
        float* __restrict__ out) {
    extern __shared__ __align__(1024) char sm[];
    const uint32_t smem_u32 = (uint32_t)__cvta_generic_to_shared(sm);
    float* qs  = reinterpret_cast<float*>(sm + SM_QS);
    float* vas = reinterpret_cast<float*>(sm + SM_VAS);
    float* es4 = reinterpret_cast<float*>(sm + SM_ES4);
    float* ps  = reinterpret_cast<float*>(sm + SM_PS);
    float* red = reinterpret_cast<float*>(sm + SM_RED);
    float* cst = reinterpret_cast<float*>(sm + SM_CST);
    __shared__ int s_last;

    const int tid  = threadIdx.x;
    const int bx   = blockIdx.x;
    const int row0 = bx * ROWS_PER_CTA;
    const int n    = row0 >> 11;              // row0 / 2048

    const int warp = tid >> 5;
    const int lane = tid & 31;
    const int wr = warp >> 2;          // 0..1 : 64-row strip
    const int wc = warp & 3;           // 0..3 : 32-col strip
    const int g  = lane >> 2;
    const int t  = lane & 3;

    // ldmatrix per-lane addressing (16B segments, SW128-swizzled rows)
    const int swz  = (lane & 7) << 4;
    const int rowA = lane & 15;
    const int hiA  = (lane >> 4) << 4;
    const int rowB = (lane & 7) + ((lane >> 4) << 3);
    const int hiB  = ((lane >> 3) & 1) << 4;

    const uint32_t mbf = smem_u32 + SM_MBAR;        // full[s] at +s*8
    const uint32_t mbe = smem_u32 + SM_MBAR + 24;   // empty[s] at +s*8

    if (tid == 0) {
#pragma unroll
        for (int s = 0; s < NSTAGE; ++s) {
            mbar_init(mbf + s * 8, 1);     // flipped by expect_tx + TMA complete
            mbar_init(mbe + s * 8, 8);     // flipped by 8 warp arrivals
        }
    }
    if (tid < HH) {
        vas[tid] = va[tid];
        qs[tid]  = g_q[n * HH + tid];
    }
    __syncthreads();   // mbarrier init + qs visible

    // prologue: 2 chunks in flight (buffers empty at start -> no empty-wait)
    if (tid == 0) {
        mbar_expect_tx(mbf + 0, STAGE_TX);
        tma2d(smem_u32 + SM_A, &tmA, 0, row0, mbf + 0);
        tma2d(smem_u32 + SM_B, &tmB, 0, 0, mbf + 0);
        mbar_expect_tx(mbf + 8, STAGE_TX);
        tma2d(smem_u32 + SM_A + A_STAGE_BYTES, &tmA, KCHUNK, row0, mbf + 8);
        tma2d(smem_u32 + SM_B + B_STAGE_BYTES, &tmB, KCHUNK, 0, mbf + 8);
    }

    float acc[4][4][4];
#pragma unroll
    for (int m = 0; m < 4; ++m)
#pragma unroll
        for (int j = 0; j < 4; ++j)
#pragma unroll
            for (int c = 0; c < 4; ++c) acc[m][j][c] = 0.f;

    const uint32_t a_tile_off = (uint32_t)((wr * 64 + rowA) * 128);
    const uint32_t b_tile_off = (uint32_t)((wc * 32 + rowB) * 128);

    // ---- mainloop: no block-wide sync; per-warp full/empty protocol ----
#pragma unroll 1
    for (int kc = 0; kc < NCHUNKS; ++kc) {
        const int s = kc - (kc / NSTAGE) * NSTAGE;      // kc % 3
        const int phase = (kc / NSTAGE) & 1;

        // producer: issue chunk kc+2 into its stage after that stage drains
        if (tid == 0 && kc + 2 < NCHUNKS) {
            const int c  = kc + 2;
            int ns = c - (c / NSTAGE) * NSTAGE;
            if (c >= NSTAGE)                            // stage had a prior occupant
                mbar_wait(mbe + ns * 8, (uint32_t)(((c - NSTAGE) / NSTAGE) & 1));
            mbar_expect_tx(mbf + ns * 8, STAGE_TX);
            tma2d(smem_u32 + SM_A + ns * A_STAGE_BYTES, &tmA, c * KCHUNK, row0, mbf + ns * 8);
            tma2d(smem_u32 + SM_B + ns * B_STAGE_BYTES, &tmB, c * KCHUNK, 0, mbf + ns * 8);
        }

        mbar_wait(mbf + s * 8, (uint32_t)phase);        // chunk kc resident

        const uint32_t abase = smem_u32 + SM_A + s * A_STAGE_BYTES + a_tile_off;
        const uint32_t bbase = smem_u32 + SM_B + s * B_STAGE_BYTES + b_tile_off;

#pragma unroll
        for (int ks = 0; ks < 4; ++ks) {
            const uint32_t colA = (uint32_t)((ks * 32 + hiA) ^ swz);
            const uint32_t colB = (uint32_t)((ks * 32 + hiB) ^ swz);

            uint32_t bu[4][2];
#pragma unroll
            for (int jj = 0; jj < 2; ++jj) {
                ldsm_x4(bu[2*jj][0], bu[2*jj][1], bu[2*jj+1][0], bu[2*jj+1][1],
                        bbase + (uint32_t)(jj * 16 * 128) + colB);
            }
#pragma unroll
            for (int m = 0; m < 4; ++m) {
                uint32_t au[4];
                ldsm_x4(au[0], au[1], au[2], au[3],
                        abase + (uint32_t)(m * 16 * 128) + colA);
#pragma unroll
                for (int j = 0; j < 4; ++j) mma_tf32(acc[m][j], au, bu[j]);
            }
        }
        if (lane == 0) mbar_arrive(mbe + s * 8);        // this warp done with stage s
    }

    // ---- epilogue: e_r = sum_h va[h] * tanh(q[h] + C[r,h]) ; per-wc partials ----
#pragma unroll
    for (int m = 0; m < 4; ++m) {
#pragma unroll
        for (int rr = 0; rr < 2; ++rr) {
            float pa = 0.f;
#pragma unroll
            for (int j = 0; j < 4; ++j) {
#pragma unroll
                for (int cc = 0; cc < 2; ++cc) {
                    int h = wc * 32 + j * 8 + t * 2 + cc;
                    pa += vas[h] * tanh_fast(qs[h] + acc[m][j][rr * 2 + cc]);
                }
            }
            pa += __shfl_xor_sync(0xffffffffu, pa, 1);
            pa += __shfl_xor_sync(0xffffffffu, pa, 2);
            if (t == 0) es4[wc * 128 + wr * 64 + m * 16 + rr * 8 + g] = pa;
        }
    }
    __syncthreads();

    // energies bounded (|e| <= sum|va| ~= 11): exp without max-pass is safe
    if (tid < ROWS_PER_CTA) {
        float e = es4[tid] + es4[128 + tid] + es4[256 + tid] + es4[384 + tid];
        float p = __expf(e);
        ps[tid] = p;
        g_p[row0 + tid] = p;
        float s = p;
#pragma unroll
        for (int o = 16; o > 0; o >>= 1) s += __shfl_xor_sync(0xffffffffu, s, o);
        if (lane == 0) red[warp] = s;
    }
    __syncthreads();
    if (tid == 0) {
        float Z = 0.f;
#pragma unroll
        for (int i = 0; i < 4; ++i) Z += red[i];
        g_pz[bx] = Z;
    }
    __syncthreads();   // ps[] visible

    // ---- partial context: 2 row-halves of 64, then smem combine ----
    {
        const int c4 = (tid & 127) * 4;
        const int half = tid >> 7;               // 0 or 1
        const float* Xp = X + (size_t)(row0 + half * 64) * QK + c4;
        float4 a = make_float4(0.f, 0.f, 0.f, 0.f);
#pragma unroll 8
        for (int l = 0; l < 64; ++l) {
            float pl = ps[half * 64 + l];
            float4 x = *reinterpret_cast<const float4*>(Xp + (size_t)l * QK);
            a.x += pl * x.x; a.y += pl * x.y; a.z += pl * x.z; a.w += pl * x.w;
        }
        if (half == 1) *reinterpret_cast<float4*>(cst + c4) = a;
        __syncthreads();
        if (half == 0) {
            float4 b = *reinterpret_cast<const float4*>(cst + c4);
            a.x += b.x; a.y += b.y; a.z += b.z; a.w += b.w;
            *reinterpret_cast<float4*>(&g_pc[(size_t)bx * QK + c4]) = a;
        }
    }

    // ---- fan-in: last CTA of the batch combines ----
    __syncthreads();
    if (tid == 0) {
        __threadfence();
        int old = atomicAdd(&g_cnt[n], 1);
        s_last = (old == SPLITS - 1) ? 1 : 0;
    }
    __syncthreads();
    if (s_last) {
        __threadfence();
        float Z = 0.f;
#pragma unroll
        for (int i = 0; i < SPLITS; ++i) Z += g_pz[n * SPLITS + i];
        const float rZ = 1.f / Z;

        float* ctx = out;                       // (NB, QK)
        float* wts = out + (size_t)NB * QK;     // (NB, LL)
#pragma unroll
        for (int dd = 0; dd < QK / THREADS; ++dd) {
            int d = tid + dd * THREADS;
            float c = 0.f;
#pragma unroll
            for (int i = 0; i < SPLITS; ++i)
                c += g_pc[(size_t)(n * SPLITS + i) * QK + d];
            ctx[(size_t)n * QK + d] = c * rZ;
        }
#pragma unroll
        for (int i = 0; i < LL / THREADS; ++i) {
            int l = tid + i * THREADS;
            wts[(size_t)n * LL + l] = g_p[(size_t)n * LL + l] * rZ;
        }
        if (tid == 0) g_cnt[n] = 0;   // self-reset for next replay
    }
}

// ---------------- host: tensormap encode via runtime entry point (no -lcuda) ----------------
typedef CUresult (*tmap_encode_t)(
    CUtensorMap*, CUtensorMapDataType, cuuint32_t, void*,
    const cuuint64_t*, const cuuint64_t*, const cuuint32_t*, const cuuint32_t*,
    CUtensorMapInterleave, CUtensorMapSwizzle, CUtensorMapL2promotion, CUtensorMapFloatOOBfill);

extern "C" void kernel_launch(void* const* d_in, const int* in_sizes, int n_in,
                              void* d_out, int out_size) {
    const float* last_hidden     = (const float*)d_in[0];
    const float* encoder_outputs = (const float*)d_in[1];
    const float* Wa              = (const float*)d_in[2];
    const float* Ua              = (const float*)d_in[3];
    const float* va              = (const float*)d_in[4];
    float* out = (float*)d_out;

    static tmap_encode_t encode = nullptr;
    static bool attr_set = false;
    if (!attr_set) {
        cudaFuncSetAttribute(k_fused, cudaFuncAttributeMaxDynamicSharedMemorySize, SM_TOTAL);
        cudaDriverEntryPointQueryResult qr;
        void* fp = nullptr;
        cudaGetDriverEntryPoint("cuTensorMapEncodeTiled", &fp, cudaEnableDefault, &qr);
        encode = (tmap_encode_t)fp;
        attr_set = true;
    }

    CUtensorMap tmA, tmB;
    {
        cuuint64_t dims[2]   = {QK, (cuuint64_t)NB * LL};
        cuuint64_t stride[1] = {QK * sizeof(float)};
        cuuint32_t box[2]    = {KCHUNK, ROWS_PER_CTA};
        cuuint32_t elems[2]  = {1, 1};
        encode(&tmA, CU_TENSOR_MAP_DATA_TYPE_FLOAT32, 2, (void*)encoder_outputs,
               dims, stride, box, elems,
               CU_TENSOR_MAP_INTERLEAVE_NONE, CU_TENSOR_MAP_SWIZZLE_128B,
               CU_TENSOR_MAP_L2_PROMOTION_L2_128B, CU_TENSOR_MAP_FLOAT_OOB_FILL_NONE);
    }
    {
        cuuint64_t dims[2]   = {QK, HH};
        cuuint64_t stride[1] = {QK * sizeof(float)};
        cuuint32_t box[2]    = {KCHUNK, HH};
        cuuint32_t elems[2]  = {1, 1};
        encode(&tmB, CU_TENSOR_MAP_DATA_TYPE_FLOAT32, 2, (void*)Ua,
               dims, stride, box, elems,
               CU_TENSOR_MAP_INTERLEAVE_NONE, CU_TENSOR_MAP_SWIZZLE_128B,
               CU_TENSOR_MAP_L2_PROMOTION_L2_128B, CU_TENSOR_MAP_FLOAT_OOB_FILL_NONE);
    }

    k_qproj<<<NB, 512>>>(last_hidden, Wa);
    k_fused<<<NCTAS, THREADS, SM_TOTAL>>>(tmA, tmB, encoder_outputs, va, out);
}